// round 6
// baseline (speedup 1.0000x reference)
#include <cuda_runtime.h>
#include <stdint.h>

#define NANCH 9
#define NPIX  1024
#define NBOX  9216          // NPIX * NANCH
#define NWORDS 144          // u64 col-words per row (= 288 u32 words)
#define SORT_CAP 16384
#define W1ELEMS (9*1280*256)

// packed f32x2 FMA (full-rate fp32 path on sm_103a)
#define FMA2(acc, a, b) asm("fma.rn.f32x2 %0, %1, %2, %0;" : "+l"(acc) : "l"(a), "l"(b))

__device__ __forceinline__ unsigned long long dup2(float a) {
    unsigned long long r;
    asm("mov.b64 %0, {%1, %1};" : "=l"(r) : "r"(__float_as_uint(a)));
    return r;
}

// ---------------- device scratch ----------------
__device__ float g_w1t[W1ELEMS];                 // w1 repacked [tap][c][oc]
__device__ float g_hp[9][256 * NPIX];            // conv1 partial sums per tap
__device__ float g_ht[NPIX * 256];               // activated hidden, transposed [p][c]
__device__ float g_raw[45 * NPIX];               // conv2 raw sums [a*5+f][p]
__device__ float g_boxes[NBOX * 4];
__device__ float g_conf[NBOX];
__device__ float g_sbox[NBOX * 4];               // boxes in sorted order
__device__ unsigned long long g_items[SORT_CAP]; // (~conf_bits<<32)|idx
__device__ int g_count;
__device__ unsigned long long g_mask[(size_t)NBOX * NWORDS];

__global__ void k_dummy() {}

// ---------------- repack w1 (o,c,t)->(t,c,o) via smem transpose + init ----------------
// grid 1280 (= 8 o-blocks x 160 c-blocks), 256 threads
__global__ void __launch_bounds__(256) k_repack(const float* __restrict__ w1) {
    __shared__ float s[9][8][33];
    const int bid = blockIdx.x;
    const int ob = bid & 7, cb = bid >> 3;
    const int tid = threadIdx.x;
    const int gi = bid * 256 + tid;
    if (gi < SORT_CAP) g_items[gi] = ~0ULL;
    if (gi == 0)       g_count = 0;

    const int o = tid >> 3, c = tid & 7;
    const float* src = w1 + ((size_t)(ob * 32 + o) * 1280 + cb * 8 + c) * 9;
#pragma unroll
    for (int t = 0; t < 9; t++) s[t][c][o] = src[t];
    __syncthreads();
#pragma unroll
    for (int k = 0; k < 9; k++) {
        int widx = tid + k * 256;
        int t   = widx >> 8;
        int rem = widx & 255;
        int cc  = rem >> 5, oo = rem & 31;
        g_w1t[(size_t)t * (1280 * 256) + (cb * 8 + cc) * 256 + ob * 32 + oo] = s[t][cc][oo];
    }
}

// ---------------- conv1: per-tap 128oc x 128px GEMM tile, f32x2 (round-4 version) ----------------
// grid (2, 8, 9), 256 threads, 8 oc x 8 px per thread, K-tile 16
__global__ void __launch_bounds__(256) k_conv1(const float* __restrict__ feat) {
    __shared__ float As[2][16][128];
    __shared__ float Bs[2][16][128];

    const int ocBase = blockIdx.x * 128;
    const int p0     = blockIdx.y * 128;
    const int tp     = blockIdx.z;
    const int dy = tp / 3 - 1, dx = tp % 3 - 1;
    const int sh = dy * 32 + dx;

    const int tid = threadIdx.x;
    const int arow = tid >> 5;
    const int acol = (tid & 31) * 4;
    const int bpx  = tid & 127;
    const int brow = tid >> 7;
    const int p    = p0 + bpx;
    const int yy   = (p >> 5) + dy;
    const int xx   = (p & 31) + dx;
    const bool bok = ((unsigned)yy < 32u) && ((unsigned)xx < 32u);
    const int bsrc = p + sh;

    const float* wp = g_w1t + (size_t)tp * (1280 * 256) + ocBase;

    const int ty = tid >> 4;
    const int tx = tid & 15;

    unsigned long long acc[8][4];
#pragma unroll
    for (int i = 0; i < 8; i++)
#pragma unroll
        for (int j = 0; j < 4; j++) acc[i][j] = 0ull;

    float4 a_reg0, a_reg1;
    float  b_reg[8];

    a_reg0 = *(const float4*)(wp + arow * 256 + acol);
    a_reg1 = *(const float4*)(wp + (arow + 8) * 256 + acol);
#pragma unroll
    for (int i = 0; i < 8; i++) {
        int c = brow + i * 2;
        b_reg[i] = bok ? feat[c * 1024 + bsrc] : 0.f;
    }

    int buf = 0;
    for (int c0 = 0; c0 < 1280; c0 += 16) {
        *(float4*)&As[buf][arow][acol]     = a_reg0;
        *(float4*)&As[buf][arow + 8][acol] = a_reg1;
#pragma unroll
        for (int i = 0; i < 8; i++) Bs[buf][brow + i * 2][bpx] = b_reg[i];
        __syncthreads();

        if (c0 + 16 < 1280) {
            const int cn = c0 + 16;
            a_reg0 = *(const float4*)(wp + (cn + arow) * 256 + acol);
            a_reg1 = *(const float4*)(wp + (cn + arow + 8) * 256 + acol);
#pragma unroll
            for (int i = 0; i < 8; i++) {
                int c = cn + brow + i * 2;
                b_reg[i] = bok ? feat[c * 1024 + bsrc] : 0.f;
            }
        }

#pragma unroll
        for (int kk = 0; kk < 16; ++kk) {
            float4 a0 = *(const float4*)&As[buf][kk][ty * 8];
            float4 a1 = *(const float4*)&As[buf][kk][ty * 8 + 4];
            ulonglong2 bq0 = *(const ulonglong2*)&Bs[buf][kk][tx * 8];
            ulonglong2 bq1 = *(const ulonglong2*)&Bs[buf][kk][tx * 8 + 4];
            unsigned long long d;
            d = dup2(a0.x); FMA2(acc[0][0], d, bq0.x); FMA2(acc[0][1], d, bq0.y); FMA2(acc[0][2], d, bq1.x); FMA2(acc[0][3], d, bq1.y);
            d = dup2(a0.y); FMA2(acc[1][0], d, bq0.x); FMA2(acc[1][1], d, bq0.y); FMA2(acc[1][2], d, bq1.x); FMA2(acc[1][3], d, bq1.y);
            d = dup2(a0.z); FMA2(acc[2][0], d, bq0.x); FMA2(acc[2][1], d, bq0.y); FMA2(acc[2][2], d, bq1.x); FMA2(acc[2][3], d, bq1.y);
            d = dup2(a0.w); FMA2(acc[3][0], d, bq0.x); FMA2(acc[3][1], d, bq0.y); FMA2(acc[3][2], d, bq1.x); FMA2(acc[3][3], d, bq1.y);
            d = dup2(a1.x); FMA2(acc[4][0], d, bq0.x); FMA2(acc[4][1], d, bq0.y); FMA2(acc[4][2], d, bq1.x); FMA2(acc[4][3], d, bq1.y);
            d = dup2(a1.y); FMA2(acc[5][0], d, bq0.x); FMA2(acc[5][1], d, bq0.y); FMA2(acc[5][2], d, bq1.x); FMA2(acc[5][3], d, bq1.y);
            d = dup2(a1.z); FMA2(acc[6][0], d, bq0.x); FMA2(acc[6][1], d, bq0.y); FMA2(acc[6][2], d, bq1.x); FMA2(acc[6][3], d, bq1.y);
            d = dup2(a1.w); FMA2(acc[7][0], d, bq0.x); FMA2(acc[7][1], d, bq0.y); FMA2(acc[7][2], d, bq1.x); FMA2(acc[7][3], d, bq1.y);
        }
        buf ^= 1;
    }

    const int oc = ocBase + ty * 8;
    const int px = p0 + tx * 8;
#pragma unroll
    for (int i = 0; i < 8; i++) {
        float* dst = g_hp[tp] + (size_t)(oc + i) * 1024 + px;
#pragma unroll
        for (int j = 0; j < 4; j++)
            *(unsigned long long*)(dst + 2 * j) = acc[i][j];
    }
}

// ---------------- combine partials + bias + lrelu + transpose to [p][c] ----------------
// grid (32, 8), block (32, 8)
__global__ void k_act(const float* __restrict__ b1) {
    __shared__ float s[32][33];
    const int tx = threadIdx.x, ty = threadIdx.y;
    const int p0 = blockIdx.x * 32, c0 = blockIdx.y * 32;
#pragma unroll
    for (int r = 0; r < 4; r++) {
        int c = c0 + ty + r * 8;
        int idx = c * 1024 + p0 + tx;
        float v = g_hp[0][idx];
#pragma unroll
        for (int z = 1; z < 9; z++) v += g_hp[z][idx];
        v += b1[c];
        v = (v > 0.f) ? v : 0.01f * v;
        s[ty + r * 8][tx] = v;   // s[c_local][p_local]
    }
    __syncthreads();
#pragma unroll
    for (int r = 0; r < 4; r++) {
        int pl = ty + r * 8;
        g_ht[(size_t)(p0 + pl) * 256 + c0 + tx] = s[tx][pl];
    }
}

// ---------------- conv2a: per-(anchor,field) dot products ----------------
// grid 180 (= 45 af x 4 p-quarters), 256 threads
__global__ void __launch_bounds__(256) k_conv2a(const float* __restrict__ w2,
                                                const float* __restrict__ b2) {
    __shared__ float w[256];
    const int b = blockIdx.x;
    const int af = b >> 2, pq = b & 3;
    const int a = af / 5, f = af - a * 5;
    const int F[5] = {0, 2, 3, 4, 5};
    const int ch = a * 6 + F[f];
    w[threadIdx.x] = w2[ch * 256 + threadIdx.x];
    __syncthreads();
    const int p = pq * 256 + threadIdx.x;
    const float4* hp = (const float4*)(g_ht + (size_t)p * 256);
    float s = 0.f;
#pragma unroll 8
    for (int i = 0; i < 64; i++) {
        float4 h = hp[i];
        s = fmaf(w[4 * i],     h.x, s);
        s = fmaf(w[4 * i + 1], h.y, s);
        s = fmaf(w[4 * i + 2], h.z, s);
        s = fmaf(w[4 * i + 3], h.w, s);
    }
    g_raw[af * 1024 + p] = s + b2[ch];
}

// ---------------- decode: sigmoid + boxes + compaction ----------------
__global__ void __launch_bounds__(256) k_decode(const float* __restrict__ anch) {
    const int i = blockIdx.x * 256 + threadIdx.x;   // < 9216
    const int a = i >> 10, p = i & 1023;
    float logit = g_raw[(a * 5 + 0) * 1024 + p];
    float tx    = g_raw[(a * 5 + 1) * 1024 + p];
    float ty    = g_raw[(a * 5 + 2) * 1024 + p];
    float tw    = g_raw[(a * 5 + 3) * 1024 + p];
    float th    = g_raw[(a * 5 + 4) * 1024 + p];
    float aw = anch[a * 2 + 0], ah = anch[a * 2 + 1];
    float cx = (float)(p & 31) + 0.5f;
    float cy = (float)(p >> 5) + 0.5f;
    float pcx = cx + tx * aw;
    float pcy = cy + ty * ah;
    float pw = aw * expf(tw);
    float ph = ah * expf(th);
    float conf = 1.0f / (1.0f + expf(-logit));
    int r = p * 9 + a;
    g_boxes[r * 4 + 0] = pcx - pw * 0.5f;
    g_boxes[r * 4 + 1] = pcy - ph * 0.5f;
    g_boxes[r * 4 + 2] = pcx + pw * 0.5f;
    g_boxes[r * 4 + 3] = pcy + ph * 0.5f;
    g_conf[r] = conf;
    if (conf > 0.5f) {
        int j = atomicAdd(&g_count, 1);
        unsigned int sb = __float_as_uint(conf);
        g_items[j] = ((unsigned long long)(~sb) << 32) | (unsigned int)r;
    }
}

// ---------------- bitonic sort (ascending), 4096-elem shared chunks ----------------
__global__ void __launch_bounds__(1024) k_sort_local4k() {
    if (blockIdx.x >= 2 && g_count <= 8192) return;   // pad region already sorted
    __shared__ unsigned long long s[4096];
    const int base = blockIdx.x * 4096;
    const int tid = threadIdx.x;
#pragma unroll
    for (int e = 0; e < 4; e++) s[tid + e * 1024] = g_items[base + tid + e * 1024];
    __syncthreads();
    for (int k = 2; k <= 4096; k <<= 1) {
        for (int j = k >> 1; j > 0; j >>= 1) {
#pragma unroll
            for (int e = 0; e < 2; e++) {
                int t = tid + e * 1024;
                int i = ((t & ~(j - 1)) << 1) | (t & (j - 1));
                int l = i + j;
                bool up = (((base + i) & k) == 0);
                unsigned long long x = s[i], y = s[l];
                if (up ? (x > y) : (x < y)) { s[i] = y; s[l] = x; }
            }
            __syncthreads();
        }
    }
#pragma unroll
    for (int e = 0; e < 4; e++) g_items[base + tid + e * 1024] = s[tid + e * 1024];
}

__global__ void __launch_bounds__(1024) k_sort_global(int k, int j, int minN) {
    if (g_count <= minN) return;
    int t = blockIdx.x * 1024 + threadIdx.x;
    int i = ((t & ~(j - 1)) << 1) | (t & (j - 1));
    int l = i + j;
    bool up = ((i & k) == 0);
    unsigned long long x = g_items[i], y = g_items[l];
    if (up ? (x > y) : (x < y)) { g_items[i] = y; g_items[l] = x; }
}

__global__ void __launch_bounds__(1024) k_sort_finish4k(int k, int minN) {
    if (g_count <= minN) return;
    __shared__ unsigned long long s[4096];
    const int base = blockIdx.x * 4096;
    const int tid = threadIdx.x;
#pragma unroll
    for (int e = 0; e < 4; e++) s[tid + e * 1024] = g_items[base + tid + e * 1024];
    __syncthreads();
    for (int j = 2048; j > 0; j >>= 1) {
#pragma unroll
        for (int e = 0; e < 2; e++) {
            int t = tid + e * 1024;
            int i = ((t & ~(j - 1)) << 1) | (t & (j - 1));
            int l = i + j;
            bool up = (((base + i) & k) == 0);
            unsigned long long x = s[i], y = s[l];
            if (up ? (x > y) : (x < y)) { s[i] = y; s[l] = x; }
        }
        __syncthreads();
    }
#pragma unroll
    for (int e = 0; e < 4; e++) g_items[base + tid + e * 1024] = s[tid + e * 1024];
}

// ---------------- stage boxes into sorted order ----------------
__global__ void __launch_bounds__(256) k_stage() {
    const int i = blockIdx.x * 256 + threadIdx.x;
    if (i >= g_count) return;
    int r = (unsigned int)g_items[i];
    ((float4*)g_sbox)[i] = *(const float4*)&g_boxes[r * 4];
}

// ---------------- NMS bitmask build: warp-ballot, 32-bit words ----------------
// grid 144 (row-blocks of 64), 256 threads = 8 warps x 8 rows each
__global__ void __launch_bounds__(256) k_mask32() {
    const int n = g_count;
    const int rb = blockIdx.x;
    if (rb * 64 >= n) return;
    __shared__ float4 srow[64];
    const int tid = threadIdx.x;
    if (tid < 64) {
        int row = rb * 64 + tid;
        srow[tid] = (row < n) ? ((const float4*)g_sbox)[row] : make_float4(0.f, 0.f, 0.f, 0.f);
    }
    __syncthreads();
    const int wrp = tid >> 5, lane = tid & 31;
    const int nbw = (n + 31) >> 5;          // 32-bit col words
    unsigned int* m32 = (unsigned int*)g_mask;

    // preload this warp's 8 row boxes + areas
    float4 bi[8]; float areai[8]; int row0 = rb * 64 + wrp * 8;
#pragma unroll
    for (int r8 = 0; r8 < 8; r8++) {
        bi[r8] = srow[wrp * 8 + r8];
        areai[r8] = fmaxf(bi[r8].z - bi[r8].x, 0.f) * fmaxf(bi[r8].w - bi[r8].y, 0.f);
    }

    for (int cw = rb * 2; cw < nbw; cw++) {
        int col = cw * 32 + lane;
        float4 bc = (col < n) ? ((const float4*)g_sbox)[col] : make_float4(0.f, 0.f, 0.f, 0.f);
        float areac = fmaxf(bc.z - bc.x, 0.f) * fmaxf(bc.w - bc.y, 0.f);
#pragma unroll
        for (int r8 = 0; r8 < 8; r8++) {
            int row = row0 + r8;
            float iw = fmaxf(fminf(bi[r8].z, bc.z) - fmaxf(bi[r8].x, bc.x), 0.f);
            float ih = fmaxf(fminf(bi[r8].w, bc.w) - fmaxf(bi[r8].y, bc.y), 0.f);
            float inter = iw * ih;
            float iou = inter / (areai[r8] + areac - inter + 1e-8f);
            bool pred = (iou > 0.7f) && (col > row);
            unsigned int word = __ballot_sync(0xffffffff, pred);
            if (lane == 0 && row < n) m32[(size_t)row * (NWORDS * 2) + cw] = word;
        }
    }
}

// ---------------- greedy NMS reduce + output ----------------
__global__ void __launch_bounds__(256) k_reduce(float* __restrict__ out) {
    __shared__ unsigned long long s_remv[NWORDS];
    __shared__ unsigned long long s_diag[2][64];
    __shared__ unsigned long long s_keepw;
    __shared__ unsigned int s_keepbox[NBOX / 32];
    const int n = g_count;
    const int nb = (n + 63) >> 6;
    const int tid = threadIdx.x;
    for (int i = tid; i < NWORDS; i += 256) s_remv[i] = 0;
    for (int i = tid; i < NBOX / 32; i += 256) s_keepbox[i] = 0;
    if (tid < 64) s_diag[0][tid] = (tid < n) ? g_mask[(size_t)tid * NWORDS] : 0ULL;
    __syncthreads();
    const int q   = tid & 3;
    const int off = tid >> 2;
    for (int w = 0; w < nb; ++w) {
        const int pb = w & 1;
        if (tid >= 64 && tid < 128) {
            int t2 = tid - 64;
            int w1 = w + 1;
            if (w1 < nb) {
                int row = w1 * 64 + t2;
                s_diag[pb ^ 1][t2] = (row < n) ? g_mask[(size_t)row * NWORDS + w1] : 0ULL;
            }
        }
        if (tid == 0) {
            unsigned long long cur = s_remv[w];
            int rem = n - w * 64;
            if (rem < 64) cur |= (~0ULL) << rem;
            unsigned long long keepw = 0;
            unsigned long long alive = ~cur;
            while (alive) {
                int b = __ffsll((long long)alive) - 1;
                keepw |= 1ULL << b;
                cur |= s_diag[pb][b];
                alive = (~cur) & ~((2ULL << b) - 1ULL);
            }
            s_keepw = keepw;
        }
        __syncthreads();
        const unsigned long long kw = s_keepw;
        for (int w2 = w + 1 + off; w2 < nb; w2 += 64) {
            unsigned long long accv = 0;
#pragma unroll
            for (int bb = 0; bb < 16; ++bb) {
                int b = q * 16 + bb;
                if ((kw >> b) & 1ULL)
                    accv |= g_mask[(size_t)(w * 64 + b) * NWORDS + w2];
            }
            if (accv) atomicOr(&s_remv[w2], accv);
        }
        if (tid >= 128 && tid < 192) {
            int t2 = tid - 128;
            if ((kw >> t2) & 1ULL) {
                int r = (unsigned int)g_items[w * 64 + t2];
                atomicOr(&s_keepbox[r >> 5], 1u << (r & 31));
            }
        }
        __syncthreads();
    }
    // output phase
    for (int i = tid; i < NBOX; i += 256) {
        float k = ((s_keepbox[i >> 5] >> (i & 31)) & 1u) ? 1.0f : 0.0f;
        float4 b = *(const float4*)&g_boxes[i * 4];
        out[i * 5 + 0] = b.x * k;
        out[i * 5 + 1] = b.y * k;
        out[i * 5 + 2] = b.z * k;
        out[i * 5 + 3] = b.w * k;
        out[i * 5 + 4] = g_conf[i] * k;
    }
}

// ---------------- launch ----------------
extern "C" void kernel_launch(void* const* d_in, const int* in_sizes, int n_in,
                              void* d_out, int out_size) {
    const float *feat = nullptr, *anch = nullptr, *w1 = nullptr,
                *b1 = nullptr, *w2 = nullptr, *b2 = nullptr;
    for (int i = 0; i < n_in; ++i) {
        switch (in_sizes[i]) {
            case 1310720: feat = (const float*)d_in[i]; break;
            case 18:      anch = (const float*)d_in[i]; break;
            case 2949120: w1   = (const float*)d_in[i]; break;
            case 256:     b1   = (const float*)d_in[i]; break;
            case 13824:   w2   = (const float*)d_in[i]; break;
            case 54:      b2   = (const float*)d_in[i]; break;
            default: break;
        }
    }
    float* out = (float*)d_out;

    k_repack<<<1280, 256>>>(w1);                   // 0 (init folded in)
    k_dummy<<<1, 32>>>();                          // 1
    k_dummy<<<1, 32>>>();                          // 2
    k_conv1<<<dim3(2, 8, 9), 256>>>(feat);         // 3 <- ncu capture slot
    k_act<<<dim3(32, 8), dim3(32, 8)>>>(b1);       // 4
    k_conv2a<<<180, 256>>>(w2, b2);                // 5
    k_decode<<<36, 256>>>(anch);                   // 6

    k_sort_local4k<<<4, 1024>>>();
    k_sort_global<<<8, 1024>>>(8192, 4096, 4096);
    k_sort_finish4k<<<4, 1024>>>(8192, 4096);
    k_sort_global<<<8, 1024>>>(16384, 8192, 8192);
    k_sort_global<<<8, 1024>>>(16384, 4096, 8192);
    k_sort_finish4k<<<4, 1024>>>(16384, 8192);

    k_stage<<<36, 256>>>();
    k_mask32<<<144, 256>>>();
    k_reduce<<<1, 256>>>(out);
}

// round 7
// speedup vs baseline: 1.2410x; 1.2410x over previous
#include <cuda_runtime.h>
#include <stdint.h>

#define NANCH 9
#define NPIX  1024
#define NBOX  9216          // NPIX * NANCH
#define NWORDS 144          // ceil(NBOX/64)
#define SORT_CAP 16384
#define W1ELEMS (9*1280*256)

// packed f32x2 FMA (full-rate fp32 path on sm_103a)
#define FMA2(acc, a, b) asm("fma.rn.f32x2 %0, %1, %2, %0;" : "+l"(acc) : "l"(a), "l"(b))

__device__ __forceinline__ unsigned long long dup2(float a) {
    unsigned long long r;
    asm("mov.b64 %0, {%1, %1};" : "=l"(r) : "r"(__float_as_uint(a)));
    return r;
}

// ---------------- device scratch ----------------
__device__ float g_w1t[W1ELEMS];                 // w1 repacked [tap][c][oc]
__device__ float g_hp[9][256 * NPIX];            // conv1 partial sums per tap
__device__ float g_h[256 * NPIX];                // activated hidden
__device__ float g_boxes[NBOX * 4];
__device__ float g_conf[NBOX];
__device__ unsigned long long g_items[SORT_CAP]; // (~conf_bits<<32)|idx
__device__ int g_count;
__device__ unsigned long long g_mask[(size_t)NBOX * NWORDS];
__device__ unsigned char g_keep[NBOX];

// ---------------- init ----------------
__global__ void k_init() {
    int i = blockIdx.x * 256 + threadIdx.x;
    if (i < SORT_CAP) g_items[i] = ~0ULL;
    if (i < NBOX)     g_keep[i] = 0;
    if (i == 0)       g_count = 0;
}

__global__ void k_dummy() {}

// ---------------- repack w1 (o,c,t) -> (t,c,o) ----------------
__global__ void k_repack(const float* __restrict__ w1) {
    int i = blockIdx.x * 256 + threadIdx.x;
    if (i >= W1ELEMS) return;
    int o  = i & 255;
    int c  = (i >> 8) % 1280;
    int tp = i / (1280 * 256);
    g_w1t[i] = w1[(o * 1280 + c) * 9 + tp];
}

// ---------------- conv1: per-tap 128oc x 64px tile, 128 threads, 2 blocks/SM ----------------
// grid (2, 16, 9), 128 threads, 8 oc x 8 px per thread, K-tile 16, double-buffered
__global__ void __launch_bounds__(128) k_conv1(const float* __restrict__ feat) {
    __shared__ float As[2][16][128];
    __shared__ float Bs[2][16][64];

    const int ocBase = blockIdx.x * 128;
    const int p0     = blockIdx.y * 64;
    const int tp     = blockIdx.z;
    const int dy = tp / 3 - 1, dx = tp % 3 - 1;
    const int sh = dy * 32 + dx;

    const int tid = threadIdx.x;
    // A loader: 4 x float4 per thread (row = tid>>3, cols (tid&7)*16 .. +15)
    const int arow = tid >> 3;          // 0..15
    const int acol = (tid & 7) * 16;    // 0..112
    // B loader: 8 scalars per thread (rows brow+{0,2,..,14}), coalesced px
    const int bpx  = tid & 63;
    const int brow = tid >> 6;          // 0..1
    const int p    = p0 + bpx;
    const int yy   = (p >> 5) + dy;
    const int xx   = (p & 31) + dx;
    const bool bok = ((unsigned)yy < 32u) && ((unsigned)xx < 32u);
    const int bsrc = p + sh;

    const float* wp = g_w1t + (size_t)tp * (1280 * 256) + ocBase;

    // compute mapping: 16 x 8 thread grid, 8 oc x 8 px each
    const int ty = tid >> 3;   // 0..15
    const int tx = tid & 7;    // 0..7

    unsigned long long acc[8][4];
#pragma unroll
    for (int i = 0; i < 8; i++)
#pragma unroll
        for (int j = 0; j < 4; j++) acc[i][j] = 0ull;

    float4 a_reg[4];
    float  b_reg[8];

    // prologue prefetch (c0 = 0)
#pragma unroll
    for (int j = 0; j < 4; j++)
        a_reg[j] = *(const float4*)(wp + arow * 256 + acol + j * 4);
#pragma unroll
    for (int i = 0; i < 8; i++) {
        int c = brow + i * 2;
        b_reg[i] = bok ? feat[c * 1024 + bsrc] : 0.f;
    }

    int buf = 0;
    for (int c0 = 0; c0 < 1280; c0 += 16) {
#pragma unroll
        for (int j = 0; j < 4; j++)
            *(float4*)&As[buf][arow][acol + j * 4] = a_reg[j];
#pragma unroll
        for (int i = 0; i < 8; i++) Bs[buf][brow + i * 2][bpx] = b_reg[i];
        __syncthreads();

        if (c0 + 16 < 1280) {
            const int cn = c0 + 16;
#pragma unroll
            for (int j = 0; j < 4; j++)
                a_reg[j] = *(const float4*)(wp + (cn + arow) * 256 + acol + j * 4);
#pragma unroll
            for (int i = 0; i < 8; i++) {
                int c = cn + brow + i * 2;
                b_reg[i] = bok ? feat[c * 1024 + bsrc] : 0.f;
            }
        }

#pragma unroll
        for (int kk = 0; kk < 16; ++kk) {
            float4 a0 = *(const float4*)&As[buf][kk][ty * 8];
            float4 a1 = *(const float4*)&As[buf][kk][ty * 8 + 4];
            ulonglong2 bq0 = *(const ulonglong2*)&Bs[buf][kk][tx * 8];
            ulonglong2 bq1 = *(const ulonglong2*)&Bs[buf][kk][tx * 8 + 4];
            unsigned long long d;
            d = dup2(a0.x); FMA2(acc[0][0], d, bq0.x); FMA2(acc[0][1], d, bq0.y); FMA2(acc[0][2], d, bq1.x); FMA2(acc[0][3], d, bq1.y);
            d = dup2(a0.y); FMA2(acc[1][0], d, bq0.x); FMA2(acc[1][1], d, bq0.y); FMA2(acc[1][2], d, bq1.x); FMA2(acc[1][3], d, bq1.y);
            d = dup2(a0.z); FMA2(acc[2][0], d, bq0.x); FMA2(acc[2][1], d, bq0.y); FMA2(acc[2][2], d, bq1.x); FMA2(acc[2][3], d, bq1.y);
            d = dup2(a0.w); FMA2(acc[3][0], d, bq0.x); FMA2(acc[3][1], d, bq0.y); FMA2(acc[3][2], d, bq1.x); FMA2(acc[3][3], d, bq1.y);
            d = dup2(a1.x); FMA2(acc[4][0], d, bq0.x); FMA2(acc[4][1], d, bq0.y); FMA2(acc[4][2], d, bq1.x); FMA2(acc[4][3], d, bq1.y);
            d = dup2(a1.y); FMA2(acc[5][0], d, bq0.x); FMA2(acc[5][1], d, bq0.y); FMA2(acc[5][2], d, bq1.x); FMA2(acc[5][3], d, bq1.y);
            d = dup2(a1.z); FMA2(acc[6][0], d, bq0.x); FMA2(acc[6][1], d, bq0.y); FMA2(acc[6][2], d, bq1.x); FMA2(acc[6][3], d, bq1.y);
            d = dup2(a1.w); FMA2(acc[7][0], d, bq0.x); FMA2(acc[7][1], d, bq0.y); FMA2(acc[7][2], d, bq1.x); FMA2(acc[7][3], d, bq1.y);
        }
        buf ^= 1;
    }

    const int oc = ocBase + ty * 8;
    const int px = p0 + tx * 8;
#pragma unroll
    for (int i = 0; i < 8; i++) {
        float* dst = g_hp[tp] + (size_t)(oc + i) * 1024 + px;
#pragma unroll
        for (int j = 0; j < 4; j++)
            *(unsigned long long*)(dst + 2 * j) = acc[i][j];
    }
}

// ---------------- combine 9 partials + bias + leaky relu ----------------
__global__ void __launch_bounds__(256) k_act(const float* __restrict__ b1) {
    int i = blockIdx.x * 256 + threadIdx.x;   // 262144 total
    float v = g_hp[0][i];
#pragma unroll
    for (int z = 1; z < 9; z++) v += g_hp[z][i];
    v += b1[i >> 10];
    v = (v > 0.f) ? v : 0.01f * v;
    g_h[i] = v;
}

// ---------------- conv2 (1x1) + sigmoid + decode + compaction ----------------
__global__ void __launch_bounds__(64) k_conv2(const float* __restrict__ w2,
                                              const float* __restrict__ b2,
                                              const float* __restrict__ anch) {
    __shared__ float sw[5][256];
    const int t = blockIdx.x * 64 + threadIdx.x;
    const int a = t >> 10;
    const int p = t & 1023;
    const int F[5] = {0, 2, 3, 4, 5};
#pragma unroll
    for (int f = 0; f < 5; ++f)
        for (int c = threadIdx.x; c < 256; c += 64)
            sw[f][c] = w2[(a * 6 + F[f]) * 256 + c];
    __syncthreads();
    float s0 = 0.f, s1 = 0.f, s2 = 0.f, s3 = 0.f, s4 = 0.f;
#pragma unroll 4
    for (int cc = 0; cc < 256; ++cc) {
        float hv = g_h[cc * 1024 + p];
        s0 = fmaf(sw[0][cc], hv, s0);
        s1 = fmaf(sw[1][cc], hv, s1);
        s2 = fmaf(sw[2][cc], hv, s2);
        s3 = fmaf(sw[3][cc], hv, s3);
        s4 = fmaf(sw[4][cc], hv, s4);
    }
    float logit = s0 + b2[a * 6 + 0];
    float tx = s1 + b2[a * 6 + 2];
    float ty = s2 + b2[a * 6 + 3];
    float tw = s3 + b2[a * 6 + 4];
    float th = s4 + b2[a * 6 + 5];
    float aw = anch[a * 2 + 0], ah = anch[a * 2 + 1];
    float cx = (float)(p & 31) + 0.5f;
    float cy = (float)(p >> 5) + 0.5f;
    float pcx = cx + tx * aw;
    float pcy = cy + ty * ah;
    float pw = aw * expf(tw);
    float ph = ah * expf(th);
    float conf = 1.0f / (1.0f + expf(-logit));
    int r = p * 9 + a;
    g_boxes[r * 4 + 0] = pcx - pw * 0.5f;
    g_boxes[r * 4 + 1] = pcy - ph * 0.5f;
    g_boxes[r * 4 + 2] = pcx + pw * 0.5f;
    g_boxes[r * 4 + 3] = pcy + ph * 0.5f;
    g_conf[r] = conf;
    if (conf > 0.5f) {
        int j = atomicAdd(&g_count, 1);
        unsigned int sb = __float_as_uint(conf);
        g_items[j] = ((unsigned long long)(~sb) << 32) | (unsigned int)r;
    }
}

// ---------------- bitonic sort (ascending), 4096-elem shared chunks ----------------
__global__ void __launch_bounds__(1024) k_sort_local4k() {
    if (blockIdx.x >= 2 && g_count <= 8192) return;   // pad region: all keys equal
    __shared__ unsigned long long s[4096];
    const int base = blockIdx.x * 4096;
    const int tid = threadIdx.x;
#pragma unroll
    for (int e = 0; e < 4; e++) s[tid + e * 1024] = g_items[base + tid + e * 1024];
    __syncthreads();
    for (int k = 2; k <= 4096; k <<= 1) {
        for (int j = k >> 1; j > 0; j >>= 1) {
#pragma unroll
            for (int e = 0; e < 2; e++) {
                int t = tid + e * 1024;
                int i = ((t & ~(j - 1)) << 1) | (t & (j - 1));
                int l = i + j;
                bool up = (((base + i) & k) == 0);
                unsigned long long x = s[i], y = s[l];
                if (up ? (x > y) : (x < y)) { s[i] = y; s[l] = x; }
            }
            __syncthreads();
        }
    }
#pragma unroll
    for (int e = 0; e < 4; e++) g_items[base + tid + e * 1024] = s[tid + e * 1024];
}

// minN: skip phase if data already confined + sorted (suffix = equal max keys)
__global__ void __launch_bounds__(1024) k_sort_global(int k, int j, int minN) {
    if (g_count <= minN) return;
    int t = blockIdx.x * 1024 + threadIdx.x;
    int i = ((t & ~(j - 1)) << 1) | (t & (j - 1));
    int l = i + j;
    bool up = ((i & k) == 0);
    unsigned long long x = g_items[i], y = g_items[l];
    if (up ? (x > y) : (x < y)) { g_items[i] = y; g_items[l] = x; }
}

__global__ void __launch_bounds__(1024) k_sort_finish4k(int k, int minN) {
    if (g_count <= minN) return;
    __shared__ unsigned long long s[4096];
    const int base = blockIdx.x * 4096;
    const int tid = threadIdx.x;
#pragma unroll
    for (int e = 0; e < 4; e++) s[tid + e * 1024] = g_items[base + tid + e * 1024];
    __syncthreads();
    for (int j = 2048; j > 0; j >>= 1) {
#pragma unroll
        for (int e = 0; e < 2; e++) {
            int t = tid + e * 1024;
            int i = ((t & ~(j - 1)) << 1) | (t & (j - 1));
            int l = i + j;
            bool up = (((base + i) & k) == 0);
            unsigned long long x = s[i], y = s[l];
            if (up ? (x > y) : (x < y)) { s[i] = y; s[l] = x; }
        }
        __syncthreads();
    }
#pragma unroll
    for (int e = 0; e < 4; e++) g_items[base + tid + e * 1024] = s[tid + e * 1024];
}

// ---------------- NMS bitmask build ----------------
__global__ void __launch_bounds__(64) k_mask() {
    const int n = g_count;
    const int rb = blockIdx.y, cb = blockIdx.x;
    if (cb < rb) return;
    if (rb * 64 >= n) return;
    if (cb * 64 >= n) return;
    __shared__ float4 sbox[64];
    const int tid = threadIdx.x;
    const int col0 = cb * 64;
    if (col0 + tid < n) {
        int r = (unsigned int)g_items[col0 + tid];
        sbox[tid] = *(const float4*)&g_boxes[r * 4];
    }
    __syncthreads();
    const int row = rb * 64 + tid;
    if (row >= n) return;
    int rr = (unsigned int)g_items[row];
    float4 bi = *(const float4*)&g_boxes[rr * 4];
    float areai = fmaxf(bi.z - bi.x, 0.f) * fmaxf(bi.w - bi.y, 0.f);
    unsigned long long bits = 0;
    int jmax = min(64, n - col0);
    for (int jj = 0; jj < jmax; ++jj) {
        int col = col0 + jj;
        if (col <= row) continue;
        float4 bj = sbox[jj];
        float iw = fmaxf(fminf(bi.z, bj.z) - fmaxf(bi.x, bj.x), 0.f);
        float ih = fmaxf(fminf(bi.w, bj.w) - fmaxf(bi.y, bj.y), 0.f);
        float inter = iw * ih;
        float areaj = fmaxf(bj.z - bj.x, 0.f) * fmaxf(bj.w - bj.y, 0.f);
        float iou = inter / (areai + areaj - inter + 1e-8f);
        if (iou > 0.7f) bits |= (1ull << jj);
    }
    g_mask[(size_t)row * NWORDS + cb] = bits;
}

// ---------------- greedy NMS reduce: ffs chain + diag prefetch ----------------
__global__ void __launch_bounds__(256) k_reduce() {
    __shared__ unsigned long long s_remv[NWORDS];
    __shared__ unsigned long long s_diag[2][64];
    __shared__ unsigned long long s_keepw;
    const int n = g_count;
    const int nb = (n + 63) >> 6;
    const int tid = threadIdx.x;
    for (int i = tid; i < NWORDS; i += 256) s_remv[i] = 0;
    if (tid < 64) s_diag[0][tid] = (tid < n) ? g_mask[(size_t)tid * NWORDS] : 0ULL;
    __syncthreads();
    const int q   = tid & 3;
    const int off = tid >> 2;
    for (int w = 0; w < nb; ++w) {
        const int pb = w & 1;
        if (tid >= 64 && tid < 128) {
            int t2 = tid - 64;
            int w1 = w + 1;
            if (w1 < nb) {
                int row = w1 * 64 + t2;
                s_diag[pb ^ 1][t2] = (row < n) ? g_mask[(size_t)row * NWORDS + w1] : 0ULL;
            }
        }
        if (tid == 0) {
            unsigned long long cur = s_remv[w];
            int rem = n - w * 64;
            if (rem < 64) cur |= (~0ULL) << rem;
            unsigned long long keepw = 0;
            unsigned long long alive = ~cur;
            while (alive) {
                int b = __ffsll((long long)alive) - 1;
                keepw |= 1ULL << b;
                cur |= s_diag[pb][b];
                alive = (~cur) & ~((2ULL << b) - 1ULL);
            }
            s_keepw = keepw;
        }
        __syncthreads();
        const unsigned long long kw = s_keepw;
        for (int w2 = w + 1 + off; w2 < nb; w2 += 64) {
            unsigned long long accv = 0;
#pragma unroll
            for (int bb = 0; bb < 16; ++bb) {
                int b = q * 16 + bb;
                if ((kw >> b) & 1ULL)
                    accv |= g_mask[(size_t)(w * 64 + b) * NWORDS + w2];
            }
            if (accv) atomicOr(&s_remv[w2], accv);
        }
        if (tid >= 128 && tid < 192) {
            int t2 = tid - 128;
            if ((kw >> t2) & 1ULL) {
                int r = (unsigned int)g_items[w * 64 + t2];
                g_keep[r] = 1;
            }
        }
        __syncthreads();
    }
}

// ---------------- final output ----------------
__global__ void __launch_bounds__(256) k_output(float* __restrict__ out) {
    int i = blockIdx.x * 256 + threadIdx.x;
    if (i >= NBOX) return;
    float k = g_keep[i] ? 1.0f : 0.0f;
    float4 b = *(const float4*)&g_boxes[i * 4];
    out[i * 5 + 0] = b.x * k;
    out[i * 5 + 1] = b.y * k;
    out[i * 5 + 2] = b.z * k;
    out[i * 5 + 3] = b.w * k;
    out[i * 5 + 4] = g_conf[i] * k;
}

// ---------------- launch ----------------
extern "C" void kernel_launch(void* const* d_in, const int* in_sizes, int n_in,
                              void* d_out, int out_size) {
    const float *feat = nullptr, *anch = nullptr, *w1 = nullptr,
                *b1 = nullptr, *w2 = nullptr, *b2 = nullptr;
    for (int i = 0; i < n_in; ++i) {
        switch (in_sizes[i]) {
            case 1310720: feat = (const float*)d_in[i]; break;
            case 18:      anch = (const float*)d_in[i]; break;
            case 2949120: w1   = (const float*)d_in[i]; break;
            case 256:     b1   = (const float*)d_in[i]; break;
            case 13824:   w2   = (const float*)d_in[i]; break;
            case 54:      b2   = (const float*)d_in[i]; break;
            default: break;
        }
    }
    float* out = (float*)d_out;

    k_init<<<64, 256>>>();                        // 0
    k_repack<<<W1ELEMS / 256, 256>>>(w1);         // 1
    k_dummy<<<1, 32>>>();                         // 2
    k_conv1<<<dim3(2, 16, 9), 128>>>(feat);       // 3 <- ncu capture slot
    k_act<<<1024, 256>>>(b1);                     // 4
    k_conv2<<<144, 64>>>(w2, b2, anch);           // 5

    k_sort_local4k<<<4, 1024>>>();
    k_sort_global<<<8, 1024>>>(8192, 4096, 4096);
    k_sort_finish4k<<<4, 1024>>>(8192, 4096);
    k_sort_global<<<8, 1024>>>(16384, 8192, 8192);
    k_sort_global<<<8, 1024>>>(16384, 4096, 8192);
    k_sort_finish4k<<<4, 1024>>>(16384, 8192);

    k_mask<<<dim3(NWORDS, NWORDS), 64>>>();
    k_reduce<<<1, 256>>>();
    k_output<<<36, 256>>>(out);
}

// round 8
// speedup vs baseline: 1.4376x; 1.1585x over previous
#include <cuda_runtime.h>
#include <stdint.h>

#define NANCH 9
#define NPIX  1024
#define NBOX  9216          // NPIX * NANCH
#define NWORDS 144          // ceil(NBOX/64)
#define SORT_CAP 16384
#define W1ELEMS (9*1280*256)

// packed f32x2 FMA (full-rate fp32 path on sm_103a)
#define FMA2(acc, a, b) asm("fma.rn.f32x2 %0, %1, %2, %0;" : "+l"(acc) : "l"(a), "l"(b))

__device__ __forceinline__ unsigned long long dup2(float a) {
    unsigned long long r;
    asm("mov.b64 %0, {%1, %1};" : "=l"(r) : "r"(__float_as_uint(a)));
    return r;
}

// ---------------- device scratch ----------------
__device__ float g_w1t[W1ELEMS];                 // w1 repacked [tap][c][oc]
__device__ float g_hp[9][256 * NPIX];            // conv1 partial sums per tap
__device__ float g_h[256 * NPIX];                // activated hidden
__device__ float g_boxes[NBOX * 4];
__device__ float g_conf[NBOX];
__device__ unsigned long long g_items[SORT_CAP]; // (~conf_bits<<32)|idx
__device__ int g_count;
__device__ unsigned long long g_mask[(size_t)NBOX * NWORDS];
__device__ unsigned char g_keep[NBOX];

// ---------------- repack w1 (o,c,t)->(t,c,o) via smem transpose, init folded ----------------
// grid 1280 (= 8 o-blocks x 160 c-blocks), 256 threads
__global__ void __launch_bounds__(256) k_pre(const float* __restrict__ w1) {
    __shared__ float s[9][8][33];
    const int bid = blockIdx.x;
    const int ob = bid & 7, cb = bid >> 3;
    const int tid = threadIdx.x;
    const int gi = bid * 256 + tid;
    if (gi < SORT_CAP) g_items[gi] = ~0ULL;
    if (gi < NBOX)     g_keep[gi] = 0;
    if (gi == 0)       g_count = 0;

    const int o = tid >> 3, c = tid & 7;
    const float* src = w1 + ((size_t)(ob * 32 + o) * 1280 + cb * 8 + c) * 9;
#pragma unroll
    for (int t = 0; t < 9; t++) s[t][c][o] = src[t];
    __syncthreads();
#pragma unroll
    for (int k = 0; k < 9; k++) {
        int widx = tid + k * 256;
        int t   = widx >> 8;
        int rem = widx & 255;
        int cc  = rem >> 5, oo = rem & 31;
        g_w1t[(size_t)t * (1280 * 256) + (cb * 8 + cc) * 256 + ob * 32 + oo] = s[t][cc][oo];
    }
}

// ---------------- conv1: per-tap 128oc x 128px GEMM tile, f32x2 (measured-best R4 version) ----------------
// grid (2, 8, 9), 256 threads, 8 oc x 8 px per thread, K-tile 16
__global__ void __launch_bounds__(256) k_conv1(const float* __restrict__ feat) {
    __shared__ float As[2][16][128];
    __shared__ float Bs[2][16][128];

    const int ocBase = blockIdx.x * 128;
    const int p0     = blockIdx.y * 128;
    const int tp     = blockIdx.z;
    const int dy = tp / 3 - 1, dx = tp % 3 - 1;
    const int sh = dy * 32 + dx;

    const int tid = threadIdx.x;
    const int arow = tid >> 5;
    const int acol = (tid & 31) * 4;
    const int bpx  = tid & 127;
    const int brow = tid >> 7;
    const int p    = p0 + bpx;
    const int yy   = (p >> 5) + dy;
    const int xx   = (p & 31) + dx;
    const bool bok = ((unsigned)yy < 32u) && ((unsigned)xx < 32u);
    const int bsrc = p + sh;

    const float* wp = g_w1t + (size_t)tp * (1280 * 256) + ocBase;

    const int ty = tid >> 4;
    const int tx = tid & 15;

    unsigned long long acc[8][4];
#pragma unroll
    for (int i = 0; i < 8; i++)
#pragma unroll
        for (int j = 0; j < 4; j++) acc[i][j] = 0ull;

    float4 a_reg0, a_reg1;
    float  b_reg[8];

    a_reg0 = *(const float4*)(wp + arow * 256 + acol);
    a_reg1 = *(const float4*)(wp + (arow + 8) * 256 + acol);
#pragma unroll
    for (int i = 0; i < 8; i++) {
        int c = brow + i * 2;
        b_reg[i] = bok ? feat[c * 1024 + bsrc] : 0.f;
    }

    int buf = 0;
    for (int c0 = 0; c0 < 1280; c0 += 16) {
        *(float4*)&As[buf][arow][acol]     = a_reg0;
        *(float4*)&As[buf][arow + 8][acol] = a_reg1;
#pragma unroll
        for (int i = 0; i < 8; i++) Bs[buf][brow + i * 2][bpx] = b_reg[i];
        __syncthreads();

        if (c0 + 16 < 1280) {
            const int cn = c0 + 16;
            a_reg0 = *(const float4*)(wp + (cn + arow) * 256 + acol);
            a_reg1 = *(const float4*)(wp + (cn + arow + 8) * 256 + acol);
#pragma unroll
            for (int i = 0; i < 8; i++) {
                int c = cn + brow + i * 2;
                b_reg[i] = bok ? feat[c * 1024 + bsrc] : 0.f;
            }
        }

#pragma unroll
        for (int kk = 0; kk < 16; ++kk) {
            float4 a0 = *(const float4*)&As[buf][kk][ty * 8];
            float4 a1 = *(const float4*)&As[buf][kk][ty * 8 + 4];
            ulonglong2 bq0 = *(const ulonglong2*)&Bs[buf][kk][tx * 8];
            ulonglong2 bq1 = *(const ulonglong2*)&Bs[buf][kk][tx * 8 + 4];
            unsigned long long d;
            d = dup2(a0.x); FMA2(acc[0][0], d, bq0.x); FMA2(acc[0][1], d, bq0.y); FMA2(acc[0][2], d, bq1.x); FMA2(acc[0][3], d, bq1.y);
            d = dup2(a0.y); FMA2(acc[1][0], d, bq0.x); FMA2(acc[1][1], d, bq0.y); FMA2(acc[1][2], d, bq1.x); FMA2(acc[1][3], d, bq1.y);
            d = dup2(a0.z); FMA2(acc[2][0], d, bq0.x); FMA2(acc[2][1], d, bq0.y); FMA2(acc[2][2], d, bq1.x); FMA2(acc[2][3], d, bq1.y);
            d = dup2(a0.w); FMA2(acc[3][0], d, bq0.x); FMA2(acc[3][1], d, bq0.y); FMA2(acc[3][2], d, bq1.x); FMA2(acc[3][3], d, bq1.y);
            d = dup2(a1.x); FMA2(acc[4][0], d, bq0.x); FMA2(acc[4][1], d, bq0.y); FMA2(acc[4][2], d, bq1.x); FMA2(acc[4][3], d, bq1.y);
            d = dup2(a1.y); FMA2(acc[5][0], d, bq0.x); FMA2(acc[5][1], d, bq0.y); FMA2(acc[5][2], d, bq1.x); FMA2(acc[5][3], d, bq1.y);
            d = dup2(a1.z); FMA2(acc[6][0], d, bq0.x); FMA2(acc[6][1], d, bq0.y); FMA2(acc[6][2], d, bq1.x); FMA2(acc[6][3], d, bq1.y);
            d = dup2(a1.w); FMA2(acc[7][0], d, bq0.x); FMA2(acc[7][1], d, bq0.y); FMA2(acc[7][2], d, bq1.x); FMA2(acc[7][3], d, bq1.y);
        }
        buf ^= 1;
    }

    const int oc = ocBase + ty * 8;
    const int px = p0 + tx * 8;
#pragma unroll
    for (int i = 0; i < 8; i++) {
        float* dst = g_hp[tp] + (size_t)(oc + i) * 1024 + px;
#pragma unroll
        for (int j = 0; j < 4; j++)
            *(unsigned long long*)(dst + 2 * j) = acc[i][j];
    }
}

// ---------------- combine 9 partials + bias + leaky relu ----------------
__global__ void __launch_bounds__(256) k_act(const float* __restrict__ b1) {
    int i = blockIdx.x * 256 + threadIdx.x;   // 262144 total
    float v = g_hp[0][i];
#pragma unroll
    for (int z = 1; z < 9; z++) v += g_hp[z][i];
    v += b1[i >> 10];
    v = (v > 0.f) ? v : 0.01f * v;
    g_h[i] = v;
}

// ---------------- conv2 (1x1) + sigmoid + decode + compaction ----------------
__global__ void __launch_bounds__(64) k_conv2(const float* __restrict__ w2,
                                              const float* __restrict__ b2,
                                              const float* __restrict__ anch) {
    __shared__ float sw[5][256];
    const int t = blockIdx.x * 64 + threadIdx.x;
    const int a = t >> 10;
    const int p = t & 1023;
    const int F[5] = {0, 2, 3, 4, 5};
#pragma unroll
    for (int f = 0; f < 5; ++f)
        for (int c = threadIdx.x; c < 256; c += 64)
            sw[f][c] = w2[(a * 6 + F[f]) * 256 + c];
    __syncthreads();
    float s0 = 0.f, s1 = 0.f, s2 = 0.f, s3 = 0.f, s4 = 0.f;
#pragma unroll 4
    for (int cc = 0; cc < 256; ++cc) {
        float hv = g_h[cc * 1024 + p];
        s0 = fmaf(sw[0][cc], hv, s0);
        s1 = fmaf(sw[1][cc], hv, s1);
        s2 = fmaf(sw[2][cc], hv, s2);
        s3 = fmaf(sw[3][cc], hv, s3);
        s4 = fmaf(sw[4][cc], hv, s4);
    }
    float logit = s0 + b2[a * 6 + 0];
    float tx = s1 + b2[a * 6 + 2];
    float ty = s2 + b2[a * 6 + 3];
    float tw = s3 + b2[a * 6 + 4];
    float th = s4 + b2[a * 6 + 5];
    float aw = anch[a * 2 + 0], ah = anch[a * 2 + 1];
    float cx = (float)(p & 31) + 0.5f;
    float cy = (float)(p >> 5) + 0.5f;
    float pcx = cx + tx * aw;
    float pcy = cy + ty * ah;
    float pw = aw * expf(tw);
    float ph = ah * expf(th);
    float conf = 1.0f / (1.0f + expf(-logit));
    int r = p * 9 + a;
    g_boxes[r * 4 + 0] = pcx - pw * 0.5f;
    g_boxes[r * 4 + 1] = pcy - ph * 0.5f;
    g_boxes[r * 4 + 2] = pcx + pw * 0.5f;
    g_boxes[r * 4 + 3] = pcy + ph * 0.5f;
    g_conf[r] = conf;
    if (conf > 0.5f) {
        int j = atomicAdd(&g_count, 1);
        unsigned int sb = __float_as_uint(conf);
        g_items[j] = ((unsigned long long)(~sb) << 32) | (unsigned int)r;
    }
}

// ---------------- bitonic sort (ascending), 4096-elem shared chunks ----------------
__global__ void __launch_bounds__(1024) k_sort_local4k() {
    if (blockIdx.x >= 2 && g_count <= 8192) return;   // pad region: all keys equal
    __shared__ unsigned long long s[4096];
    const int base = blockIdx.x * 4096;
    const int tid = threadIdx.x;
#pragma unroll
    for (int e = 0; e < 4; e++) s[tid + e * 1024] = g_items[base + tid + e * 1024];
    __syncthreads();
    for (int k = 2; k <= 4096; k <<= 1) {
        for (int j = k >> 1; j > 0; j >>= 1) {
#pragma unroll
            for (int e = 0; e < 2; e++) {
                int t = tid + e * 1024;
                int i = ((t & ~(j - 1)) << 1) | (t & (j - 1));
                int l = i + j;
                bool up = (((base + i) & k) == 0);
                unsigned long long x = s[i], y = s[l];
                if (up ? (x > y) : (x < y)) { s[i] = y; s[l] = x; }
            }
            __syncthreads();
        }
    }
#pragma unroll
    for (int e = 0; e < 4; e++) g_items[base + tid + e * 1024] = s[tid + e * 1024];
}

__global__ void __launch_bounds__(1024) k_sort_global(int k, int j, int minN) {
    if (g_count <= minN) return;
    int t = blockIdx.x * 1024 + threadIdx.x;
    int i = ((t & ~(j - 1)) << 1) | (t & (j - 1));
    int l = i + j;
    bool up = ((i & k) == 0);
    unsigned long long x = g_items[i], y = g_items[l];
    if (up ? (x > y) : (x < y)) { g_items[i] = y; g_items[l] = x; }
}

__global__ void __launch_bounds__(1024) k_sort_finish4k(int k, int minN) {
    if (g_count <= minN) return;
    __shared__ unsigned long long s[4096];
    const int base = blockIdx.x * 4096;
    const int tid = threadIdx.x;
#pragma unroll
    for (int e = 0; e < 4; e++) s[tid + e * 1024] = g_items[base + tid + e * 1024];
    __syncthreads();
    for (int j = 2048; j > 0; j >>= 1) {
#pragma unroll
        for (int e = 0; e < 2; e++) {
            int t = tid + e * 1024;
            int i = ((t & ~(j - 1)) << 1) | (t & (j - 1));
            int l = i + j;
            bool up = (((base + i) & k) == 0);
            unsigned long long x = s[i], y = s[l];
            if (up ? (x > y) : (x < y)) { s[i] = y; s[l] = x; }
        }
        __syncthreads();
    }
#pragma unroll
    for (int e = 0; e < 4; e++) g_items[base + tid + e * 1024] = s[tid + e * 1024];
}

// ---------------- NMS bitmask build (dry=1: profiling pass, fixed n, masked indices) ----------------
__global__ void __launch_bounds__(64) k_mask(int dry) {
    const int n = dry ? 4608 : g_count;
    const int rb = blockIdx.y, cb = blockIdx.x;
    if (cb < rb) return;
    if (rb * 64 >= n) return;
    if (cb * 64 >= n) return;
    __shared__ float4 sbox[64];
    const int tid = threadIdx.x;
    const int col0 = cb * 64;
    if (col0 + tid < n) {
        int r = (unsigned int)g_items[col0 + tid];
        if (dry) r &= 8191;
        sbox[tid] = *(const float4*)&g_boxes[r * 4];
    }
    __syncthreads();
    const int row = rb * 64 + tid;
    if (row >= n) return;
    int rr = (unsigned int)g_items[row];
    if (dry) rr &= 8191;
    float4 bi = *(const float4*)&g_boxes[rr * 4];
    float areai = fmaxf(bi.z - bi.x, 0.f) * fmaxf(bi.w - bi.y, 0.f);
    unsigned long long bits = 0;
    int jmax = min(64, n - col0);
    for (int jj = 0; jj < jmax; ++jj) {
        int col = col0 + jj;
        if (col <= row) continue;
        float4 bj = sbox[jj];
        float iw = fmaxf(fminf(bi.z, bj.z) - fmaxf(bi.x, bj.x), 0.f);
        float ih = fmaxf(fminf(bi.w, bj.w) - fmaxf(bi.y, bj.y), 0.f);
        float inter = iw * ih;
        float areaj = fmaxf(bj.z - bj.x, 0.f) * fmaxf(bj.w - bj.y, 0.f);
        float iou = inter / (areai + areaj - inter + 1e-8f);
        if (iou > 0.7f) bits |= (1ull << jj);
    }
    g_mask[(size_t)row * NWORDS + cb] = bits;
}

// ---------------- greedy NMS reduce (R3 measured-best variant) ----------------
__global__ void __launch_bounds__(256) k_reduce() {
    __shared__ unsigned long long s_remv[NWORDS];
    __shared__ unsigned long long s_diag[64];
    __shared__ unsigned long long s_keepw;
    const int n = g_count;
    const int nb = (n + 63) >> 6;
    const int tid = threadIdx.x;
    for (int i = tid; i < NWORDS; i += 256) s_remv[i] = 0;
    __syncthreads();
    const int q   = tid & 3;
    const int off = tid >> 2;
    for (int w = 0; w < nb; ++w) {
        if (tid < 64) {
            int row = w * 64 + tid;
            s_diag[tid] = (row < n) ? g_mask[(size_t)row * NWORDS + w] : 0ULL;
        }
        __syncthreads();
        if (tid == 0) {
            unsigned long long cur = s_remv[w];
            int rem = n - w * 64;
            if (rem < 64) cur |= (~0ULL) << rem;
            unsigned long long keepw = 0;
#pragma unroll
            for (int b = 0; b < 64; ++b) {
                if (!((cur >> b) & 1ULL)) {
                    keepw |= 1ULL << b;
                    cur |= s_diag[b];
                }
            }
            s_remv[w] = cur;
            s_keepw = keepw;
        }
        __syncthreads();
        const unsigned long long kw = s_keepw;
        for (int w2 = w + 1 + off; w2 < nb; w2 += 64) {
            unsigned long long accv = 0;
#pragma unroll
            for (int bb = 0; bb < 16; ++bb) {
                int b = q * 16 + bb;
                if ((kw >> b) & 1ULL)
                    accv |= g_mask[(size_t)(w * 64 + b) * NWORDS + w2];
            }
            if (accv) atomicOr(&s_remv[w2], accv);
        }
        __syncthreads();
        if (tid < 64) {
            if ((kw >> tid) & 1ULL) {
                int r = (unsigned int)g_items[w * 64 + tid];
                g_keep[r] = 1;
            }
        }
        __syncthreads();
    }
}

// ---------------- final output ----------------
__global__ void __launch_bounds__(256) k_output(float* __restrict__ out) {
    int i = blockIdx.x * 256 + threadIdx.x;
    if (i >= NBOX) return;
    float k = g_keep[i] ? 1.0f : 0.0f;
    float4 b = *(const float4*)&g_boxes[i * 4];
    out[i * 5 + 0] = b.x * k;
    out[i * 5 + 1] = b.y * k;
    out[i * 5 + 2] = b.z * k;
    out[i * 5 + 3] = b.w * k;
    out[i * 5 + 4] = g_conf[i] * k;
}

// ---------------- launch ----------------
extern "C" void kernel_launch(void* const* d_in, const int* in_sizes, int n_in,
                              void* d_out, int out_size) {
    const float *feat = nullptr, *anch = nullptr, *w1 = nullptr,
                *b1 = nullptr, *w2 = nullptr, *b2 = nullptr;
    for (int i = 0; i < n_in; ++i) {
        switch (in_sizes[i]) {
            case 1310720: feat = (const float*)d_in[i]; break;
            case 18:      anch = (const float*)d_in[i]; break;
            case 2949120: w1   = (const float*)d_in[i]; break;
            case 256:     b1   = (const float*)d_in[i]; break;
            case 13824:   w2   = (const float*)d_in[i]; break;
            case 54:      b2   = (const float*)d_in[i]; break;
            default: break;
        }
    }
    float* out = (float*)d_out;

    k_pre<<<1280, 256>>>(w1);                       // 0 (repack + init)
    k_conv1<<<dim3(2, 8, 9), 256>>>(feat);          // 1
    k_act<<<1024, 256>>>(b1);                       // 2
    k_mask<<<dim3(NWORDS, NWORDS), 64>>>(1);        // 3 <- DRY RUN, ncu capture slot
    k_conv2<<<144, 64>>>(w2, b2, anch);             // 4

    k_sort_local4k<<<4, 1024>>>();                  // 5
    k_sort_global<<<8, 1024>>>(8192, 4096, 4096);   // 6
    k_sort_finish4k<<<4, 1024>>>(8192, 4096);       // 7
    k_sort_global<<<8, 1024>>>(16384, 8192, 8192);  // 8
    k_sort_global<<<8, 1024>>>(16384, 4096, 8192);  // 9
    k_sort_finish4k<<<4, 1024>>>(16384, 8192);      // 10

    k_mask<<<dim3(NWORDS, NWORDS), 64>>>(0);        // 11 (real)
    k_reduce<<<1, 256>>>();                         // 12
    k_output<<<36, 256>>>(out);                     // 13
}

// round 9
// speedup vs baseline: 1.5937x; 1.1086x over previous
#include <cuda_runtime.h>
#include <stdint.h>

#define NANCH 9
#define NPIX  1024
#define NBOX  9216          // NPIX * NANCH
#define NWORDS 144          // ceil(NBOX/64)
#define SORT_CAP 16384
#define W1ELEMS (9*1280*256)

// packed f32x2 FMA (full-rate fp32 path on sm_103a)
#define FMA2(acc, a, b) asm("fma.rn.f32x2 %0, %1, %2, %0;" : "+l"(acc) : "l"(a), "l"(b))

__device__ __forceinline__ unsigned long long dup2(float a) {
    unsigned long long r;
    asm("mov.b64 %0, {%1, %1};" : "=l"(r) : "r"(__float_as_uint(a)));
    return r;
}

// ---------------- device scratch ----------------
__device__ float g_w1t[W1ELEMS];                 // w1 repacked [tap][c][oc]
__device__ float g_hp[9][256 * NPIX];            // conv1 partial sums per tap
__device__ float g_h[256 * NPIX];                // activated hidden
__device__ float g_boxes[NBOX * 4];
__device__ float g_conf[NBOX];
__device__ unsigned long long g_items[SORT_CAP]; // (~conf_bits<<32)|idx
__device__ int g_count;
__device__ unsigned long long g_mask[(size_t)NBOX * NWORDS];
__device__ unsigned char g_keep[NBOX];

// ---------------- repack w1 (o,c,t)->(t,c,o) via smem transpose, init folded ----------------
// grid 1280 (= 8 o-blocks x 160 c-blocks), 256 threads
__global__ void __launch_bounds__(256) k_pre(const float* __restrict__ w1) {
    __shared__ float s[9][8][33];
    const int bid = blockIdx.x;
    const int ob = bid & 7, cb = bid >> 3;
    const int tid = threadIdx.x;
    const int gi = bid * 256 + tid;
    if (gi < SORT_CAP) g_items[gi] = ~0ULL;
    if (gi < NBOX)     g_keep[gi] = 0;
    if (gi == 0)       g_count = 0;

    const int o = tid >> 3, c = tid & 7;
    const float* src = w1 + ((size_t)(ob * 32 + o) * 1280 + cb * 8 + c) * 9;
#pragma unroll
    for (int t = 0; t < 9; t++) s[t][c][o] = src[t];
    __syncthreads();
#pragma unroll
    for (int k = 0; k < 9; k++) {
        int widx = tid + k * 256;
        int t   = widx >> 8;
        int rem = widx & 255;
        int cc  = rem >> 5, oo = rem & 31;
        g_w1t[(size_t)t * (1280 * 256) + (cb * 8 + cc) * 256 + ob * 32 + oo] = s[t][cc][oo];
    }
}

// ---------------- conv1: per-tap 128oc x 128px GEMM tile, f32x2 (measured-best R4 version) ----------------
// grid (2, 8, 9), 256 threads, 8 oc x 8 px per thread, K-tile 16
__global__ void __launch_bounds__(256) k_conv1(const float* __restrict__ feat) {
    __shared__ float As[2][16][128];
    __shared__ float Bs[2][16][128];

    const int ocBase = blockIdx.x * 128;
    const int p0     = blockIdx.y * 128;
    const int tp     = blockIdx.z;
    const int dy = tp / 3 - 1, dx = tp % 3 - 1;
    const int sh = dy * 32 + dx;

    const int tid = threadIdx.x;
    const int arow = tid >> 5;
    const int acol = (tid & 31) * 4;
    const int bpx  = tid & 127;
    const int brow = tid >> 7;
    const int p    = p0 + bpx;
    const int yy   = (p >> 5) + dy;
    const int xx   = (p & 31) + dx;
    const bool bok = ((unsigned)yy < 32u) && ((unsigned)xx < 32u);
    const int bsrc = p + sh;

    const float* wp = g_w1t + (size_t)tp * (1280 * 256) + ocBase;

    const int ty = tid >> 4;
    const int tx = tid & 15;

    unsigned long long acc[8][4];
#pragma unroll
    for (int i = 0; i < 8; i++)
#pragma unroll
        for (int j = 0; j < 4; j++) acc[i][j] = 0ull;

    float4 a_reg0, a_reg1;
    float  b_reg[8];

    a_reg0 = *(const float4*)(wp + arow * 256 + acol);
    a_reg1 = *(const float4*)(wp + (arow + 8) * 256 + acol);
#pragma unroll
    for (int i = 0; i < 8; i++) {
        int c = brow + i * 2;
        b_reg[i] = bok ? feat[c * 1024 + bsrc] : 0.f;
    }

    int buf = 0;
    for (int c0 = 0; c0 < 1280; c0 += 16) {
        *(float4*)&As[buf][arow][acol]     = a_reg0;
        *(float4*)&As[buf][arow + 8][acol] = a_reg1;
#pragma unroll
        for (int i = 0; i < 8; i++) Bs[buf][brow + i * 2][bpx] = b_reg[i];
        __syncthreads();

        if (c0 + 16 < 1280) {
            const int cn = c0 + 16;
            a_reg0 = *(const float4*)(wp + (cn + arow) * 256 + acol);
            a_reg1 = *(const float4*)(wp + (cn + arow + 8) * 256 + acol);
#pragma unroll
            for (int i = 0; i < 8; i++) {
                int c = cn + brow + i * 2;
                b_reg[i] = bok ? feat[c * 1024 + bsrc] : 0.f;
            }
        }

#pragma unroll
        for (int kk = 0; kk < 16; ++kk) {
            float4 a0 = *(const float4*)&As[buf][kk][ty * 8];
            float4 a1 = *(const float4*)&As[buf][kk][ty * 8 + 4];
            ulonglong2 bq0 = *(const ulonglong2*)&Bs[buf][kk][tx * 8];
            ulonglong2 bq1 = *(const ulonglong2*)&Bs[buf][kk][tx * 8 + 4];
            unsigned long long d;
            d = dup2(a0.x); FMA2(acc[0][0], d, bq0.x); FMA2(acc[0][1], d, bq0.y); FMA2(acc[0][2], d, bq1.x); FMA2(acc[0][3], d, bq1.y);
            d = dup2(a0.y); FMA2(acc[1][0], d, bq0.x); FMA2(acc[1][1], d, bq0.y); FMA2(acc[1][2], d, bq1.x); FMA2(acc[1][3], d, bq1.y);
            d = dup2(a0.z); FMA2(acc[2][0], d, bq0.x); FMA2(acc[2][1], d, bq0.y); FMA2(acc[2][2], d, bq1.x); FMA2(acc[2][3], d, bq1.y);
            d = dup2(a0.w); FMA2(acc[3][0], d, bq0.x); FMA2(acc[3][1], d, bq0.y); FMA2(acc[3][2], d, bq1.x); FMA2(acc[3][3], d, bq1.y);
            d = dup2(a1.x); FMA2(acc[4][0], d, bq0.x); FMA2(acc[4][1], d, bq0.y); FMA2(acc[4][2], d, bq1.x); FMA2(acc[4][3], d, bq1.y);
            d = dup2(a1.y); FMA2(acc[5][0], d, bq0.x); FMA2(acc[5][1], d, bq0.y); FMA2(acc[5][2], d, bq1.x); FMA2(acc[5][3], d, bq1.y);
            d = dup2(a1.z); FMA2(acc[6][0], d, bq0.x); FMA2(acc[6][1], d, bq0.y); FMA2(acc[6][2], d, bq1.x); FMA2(acc[6][3], d, bq1.y);
            d = dup2(a1.w); FMA2(acc[7][0], d, bq0.x); FMA2(acc[7][1], d, bq0.y); FMA2(acc[7][2], d, bq1.x); FMA2(acc[7][3], d, bq1.y);
        }
        buf ^= 1;
    }

    const int oc = ocBase + ty * 8;
    const int px = p0 + tx * 8;
#pragma unroll
    for (int i = 0; i < 8; i++) {
        float* dst = g_hp[tp] + (size_t)(oc + i) * 1024 + px;
#pragma unroll
        for (int j = 0; j < 4; j++)
            *(unsigned long long*)(dst + 2 * j) = acc[i][j];
    }
}

// ---------------- combine 9 partials + bias + leaky relu ----------------
__global__ void __launch_bounds__(256) k_act(const float* __restrict__ b1) {
    int i = blockIdx.x * 256 + threadIdx.x;   // 262144 total
    float v = g_hp[0][i];
#pragma unroll
    for (int z = 1; z < 9; z++) v += g_hp[z][i];
    v += b1[i >> 10];
    v = (v > 0.f) ? v : 0.01f * v;
    g_h[i] = v;
}

// ---------------- conv2 (1x1) + sigmoid + decode + compaction ----------------
__global__ void __launch_bounds__(64) k_conv2(const float* __restrict__ w2,
                                              const float* __restrict__ b2,
                                              const float* __restrict__ anch) {
    __shared__ float sw[5][256];
    const int t = blockIdx.x * 64 + threadIdx.x;
    const int a = t >> 10;
    const int p = t & 1023;
    const int F[5] = {0, 2, 3, 4, 5};
#pragma unroll
    for (int f = 0; f < 5; ++f)
        for (int c = threadIdx.x; c < 256; c += 64)
            sw[f][c] = w2[(a * 6 + F[f]) * 256 + c];
    __syncthreads();
    float s0 = 0.f, s1 = 0.f, s2 = 0.f, s3 = 0.f, s4 = 0.f;
#pragma unroll 4
    for (int cc = 0; cc < 256; ++cc) {
        float hv = g_h[cc * 1024 + p];
        s0 = fmaf(sw[0][cc], hv, s0);
        s1 = fmaf(sw[1][cc], hv, s1);
        s2 = fmaf(sw[2][cc], hv, s2);
        s3 = fmaf(sw[3][cc], hv, s3);
        s4 = fmaf(sw[4][cc], hv, s4);
    }
    float logit = s0 + b2[a * 6 + 0];
    float tx = s1 + b2[a * 6 + 2];
    float ty = s2 + b2[a * 6 + 3];
    float tw = s3 + b2[a * 6 + 4];
    float th = s4 + b2[a * 6 + 5];
    float aw = anch[a * 2 + 0], ah = anch[a * 2 + 1];
    float cx = (float)(p & 31) + 0.5f;
    float cy = (float)(p >> 5) + 0.5f;
    float pcx = cx + tx * aw;
    float pcy = cy + ty * ah;
    float pw = aw * expf(tw);
    float ph = ah * expf(th);
    float conf = 1.0f / (1.0f + expf(-logit));
    int r = p * 9 + a;
    g_boxes[r * 4 + 0] = pcx - pw * 0.5f;
    g_boxes[r * 4 + 1] = pcy - ph * 0.5f;
    g_boxes[r * 4 + 2] = pcx + pw * 0.5f;
    g_boxes[r * 4 + 3] = pcy + ph * 0.5f;
    g_conf[r] = conf;
    if (conf > 0.5f) {
        int j = atomicAdd(&g_count, 1);
        unsigned int sb = __float_as_uint(conf);
        g_items[j] = ((unsigned long long)(~sb) << 32) | (unsigned int)r;
    }
}

// ---------------- bitonic sort (ascending), 4096-elem shared chunks ----------------
__global__ void __launch_bounds__(1024) k_sort_local4k() {
    if (blockIdx.x >= 2 && g_count <= 8192) return;   // pad region: all keys equal
    __shared__ unsigned long long s[4096];
    const int base = blockIdx.x * 4096;
    const int tid = threadIdx.x;
#pragma unroll
    for (int e = 0; e < 4; e++) s[tid + e * 1024] = g_items[base + tid + e * 1024];
    __syncthreads();
    for (int k = 2; k <= 4096; k <<= 1) {
        for (int j = k >> 1; j > 0; j >>= 1) {
#pragma unroll
            for (int e = 0; e < 2; e++) {
                int t = tid + e * 1024;
                int i = ((t & ~(j - 1)) << 1) | (t & (j - 1));
                int l = i + j;
                bool up = (((base + i) & k) == 0);
                unsigned long long x = s[i], y = s[l];
                if (up ? (x > y) : (x < y)) { s[i] = y; s[l] = x; }
            }
            __syncthreads();
        }
    }
#pragma unroll
    for (int e = 0; e < 4; e++) g_items[base + tid + e * 1024] = s[tid + e * 1024];
}

__global__ void __launch_bounds__(1024) k_sort_global(int k, int j, int minN) {
    if (g_count <= minN) return;
    if (blockIdx.x >= 4 && g_count <= 8192) return;   // pad-only pairs: keys equal, no swap
    int t = blockIdx.x * 1024 + threadIdx.x;
    int i = ((t & ~(j - 1)) << 1) | (t & (j - 1));
    int l = i + j;
    bool up = ((i & k) == 0);
    unsigned long long x = g_items[i], y = g_items[l];
    if (up ? (x > y) : (x < y)) { g_items[i] = y; g_items[l] = x; }
}

__global__ void __launch_bounds__(1024) k_sort_finish4k(int k, int minN) {
    if (g_count <= minN) return;
    if (blockIdx.x >= 2 && g_count <= 8192) return;   // pad region: all keys equal
    __shared__ unsigned long long s[4096];
    const int base = blockIdx.x * 4096;
    const int tid = threadIdx.x;
#pragma unroll
    for (int e = 0; e < 4; e++) s[tid + e * 1024] = g_items[base + tid + e * 1024];
    __syncthreads();
    for (int j = 2048; j > 0; j >>= 1) {
#pragma unroll
        for (int e = 0; e < 2; e++) {
            int t = tid + e * 1024;
            int i = ((t & ~(j - 1)) << 1) | (t & (j - 1));
            int l = i + j;
            bool up = (((base + i) & k) == 0);
            unsigned long long x = s[i], y = s[l];
            if (up ? (x > y) : (x < y)) { s[i] = y; s[l] = x; }
        }
        __syncthreads();
    }
#pragma unroll
    for (int e = 0; e < 4; e++) g_items[base + tid + e * 1024] = s[tid + e * 1024];
}

// ---------------- NMS bitmask build: warp ballot, column boxes in registers ----------------
// grid (144,144) upper-triangular, 64 threads = 2 warps x 32 rows
__global__ void __launch_bounds__(64) k_mask() {
    const int n = g_count;
    const int rb = blockIdx.y, cb = blockIdx.x;
    if (cb < rb) return;
    if (rb * 64 >= n) return;
    if (cb * 64 >= n) return;
    __shared__ float4 srow[64];
    __shared__ float  sarea[64];
    const int tid = threadIdx.x;
    const int row_g = rb * 64 + tid;
    if (row_g < n) {
        int r = (unsigned int)g_items[row_g];
        float4 b = *(const float4*)&g_boxes[r * 4];
        srow[tid]  = b;
        sarea[tid] = fmaxf(b.z - b.x, 0.f) * fmaxf(b.w - b.y, 0.f);
    } else {
        srow[tid]  = make_float4(0.f, 0.f, 0.f, 0.f);
        sarea[tid] = 0.f;
    }
    __syncthreads();

    const int wrp = tid >> 5, lane = tid & 31;
    const int colA = cb * 64 + lane;
    const int colB = colA + 32;
    float4 bA = make_float4(0.f, 0.f, 0.f, 0.f);
    float4 bB = make_float4(0.f, 0.f, 0.f, 0.f);
    if (colA < n) bA = *(const float4*)&g_boxes[((unsigned int)g_items[colA]) * 4];
    if (colB < n) bB = *(const float4*)&g_boxes[((unsigned int)g_items[colB]) * 4];
    const float areaA = fmaxf(bA.z - bA.x, 0.f) * fmaxf(bA.w - bA.y, 0.f);
    const float areaB = fmaxf(bB.z - bB.x, 0.f) * fmaxf(bB.w - bB.y, 0.f);
    const bool okA = colA < n, okB = colB < n;

    const int rend = min(32, n - rb * 64 - wrp * 32);   // rows this warp writes
    for (int r8 = 0; r8 < rend; ++r8) {
        const int rl = wrp * 32 + r8;
        const int row = rb * 64 + rl;
        const float4 bi = srow[rl];
        const float ai = sarea[rl];

        float iwA = fmaxf(fminf(bi.z, bA.z) - fmaxf(bi.x, bA.x), 0.f);
        float ihA = fmaxf(fminf(bi.w, bA.w) - fmaxf(bi.y, bA.y), 0.f);
        float interA = iwA * ihA;
        float iouA = interA / (ai + areaA - interA + 1e-8f);
        bool pA = (iouA > 0.7f) && (colA > row) && okA;
        unsigned int wA = __ballot_sync(0xffffffffu, pA);

        float iwB = fmaxf(fminf(bi.z, bB.z) - fmaxf(bi.x, bB.x), 0.f);
        float ihB = fmaxf(fminf(bi.w, bB.w) - fmaxf(bi.y, bB.y), 0.f);
        float interB = iwB * ihB;
        float iouB = interB / (ai + areaB - interB + 1e-8f);
        bool pB = (iouB > 0.7f) && (colB > row) && okB;
        unsigned int wB = __ballot_sync(0xffffffffu, pB);

        if (lane == 0)
            g_mask[(size_t)row * NWORDS + cb] =
                (unsigned long long)wA | ((unsigned long long)wB << 32);
    }
}

// ---------------- greedy NMS reduce (R3 measured-best variant) ----------------
__global__ void __launch_bounds__(256) k_reduce() {
    __shared__ unsigned long long s_remv[NWORDS];
    __shared__ unsigned long long s_diag[64];
    __shared__ unsigned long long s_keepw;
    const int n = g_count;
    const int nb = (n + 63) >> 6;
    const int tid = threadIdx.x;
    for (int i = tid; i < NWORDS; i += 256) s_remv[i] = 0;
    __syncthreads();
    const int q   = tid & 3;
    const int off = tid >> 2;
    for (int w = 0; w < nb; ++w) {
        if (tid < 64) {
            int row = w * 64 + tid;
            s_diag[tid] = (row < n) ? g_mask[(size_t)row * NWORDS + w] : 0ULL;
        }
        __syncthreads();
        if (tid == 0) {
            unsigned long long cur = s_remv[w];
            int rem = n - w * 64;
            if (rem < 64) cur |= (~0ULL) << rem;
            unsigned long long keepw = 0;
#pragma unroll
            for (int b = 0; b < 64; ++b) {
                if (!((cur >> b) & 1ULL)) {
                    keepw |= 1ULL << b;
                    cur |= s_diag[b];
                }
            }
            s_remv[w] = cur;
            s_keepw = keepw;
        }
        __syncthreads();
        const unsigned long long kw = s_keepw;
        for (int w2 = w + 1 + off; w2 < nb; w2 += 64) {
            unsigned long long accv = 0;
#pragma unroll
            for (int bb = 0; bb < 16; ++bb) {
                int b = q * 16 + bb;
                if ((kw >> b) & 1ULL)
                    accv |= g_mask[(size_t)(w * 64 + b) * NWORDS + w2];
            }
            if (accv) atomicOr(&s_remv[w2], accv);
        }
        __syncthreads();
        if (tid < 64) {
            if ((kw >> tid) & 1ULL) {
                int r = (unsigned int)g_items[w * 64 + tid];
                g_keep[r] = 1;
            }
        }
        __syncthreads();
    }
}

// ---------------- final output ----------------
__global__ void __launch_bounds__(256) k_output(float* __restrict__ out) {
    int i = blockIdx.x * 256 + threadIdx.x;
    if (i >= NBOX) return;
    float k = g_keep[i] ? 1.0f : 0.0f;
    float4 b = *(const float4*)&g_boxes[i * 4];
    out[i * 5 + 0] = b.x * k;
    out[i * 5 + 1] = b.y * k;
    out[i * 5 + 2] = b.z * k;
    out[i * 5 + 3] = b.w * k;
    out[i * 5 + 4] = g_conf[i] * k;
}

// ---------------- launch ----------------
extern "C" void kernel_launch(void* const* d_in, const int* in_sizes, int n_in,
                              void* d_out, int out_size) {
    const float *feat = nullptr, *anch = nullptr, *w1 = nullptr,
                *b1 = nullptr, *w2 = nullptr, *b2 = nullptr;
    for (int i = 0; i < n_in; ++i) {
        switch (in_sizes[i]) {
            case 1310720: feat = (const float*)d_in[i]; break;
            case 18:      anch = (const float*)d_in[i]; break;
            case 2949120: w1   = (const float*)d_in[i]; break;
            case 256:     b1   = (const float*)d_in[i]; break;
            case 13824:   w2   = (const float*)d_in[i]; break;
            case 54:      b2   = (const float*)d_in[i]; break;
            default: break;
        }
    }
    float* out = (float*)d_out;

    k_pre<<<1280, 256>>>(w1);                       // 0 (repack + init)
    k_conv1<<<dim3(2, 8, 9), 256>>>(feat);          // 1
    k_act<<<1024, 256>>>(b1);                       // 2
    k_conv2<<<144, 64>>>(w2, b2, anch);             // 3 <- ncu capture slot

    k_sort_local4k<<<4, 1024>>>();                  // 4
    k_sort_global<<<8, 1024>>>(8192, 4096, 4096);   // 5
    k_sort_finish4k<<<4, 1024>>>(8192, 4096);       // 6
    k_sort_global<<<8, 1024>>>(16384, 8192, 8192);  // 7
    k_sort_global<<<8, 1024>>>(16384, 4096, 8192);  // 8
    k_sort_finish4k<<<4, 1024>>>(16384, 8192);      // 9

    k_mask<<<dim3(144, 144), 64>>>();               // 10
    k_reduce<<<1, 256>>>();                         // 11
    k_output<<<36, 256>>>(out);                     // 12
}

// round 10
// speedup vs baseline: 1.6363x; 1.0267x over previous
#include <cuda_runtime.h>
#include <stdint.h>

#define NANCH 9
#define NPIX  1024
#define NBOX  9216          // NPIX * NANCH
#define NWORDS 144          // ceil(NBOX/64)
#define SORT_CAP 16384
#define W1ELEMS (9*1280*256)

// packed f32x2 FMA (full-rate fp32 path on sm_103a)
#define FMA2(acc, a, b) asm("fma.rn.f32x2 %0, %1, %2, %0;" : "+l"(acc) : "l"(a), "l"(b))

__device__ __forceinline__ unsigned long long dup2(float a) {
    unsigned long long r;
    asm("mov.b64 %0, {%1, %1};" : "=l"(r) : "r"(__float_as_uint(a)));
    return r;
}

// ---------------- device scratch ----------------
__device__ float g_w1t[W1ELEMS];                 // w1 repacked [tap][c][oc]
__device__ float g_hp[9][256 * NPIX];            // conv1 partial sums per tap
__device__ float g_h[256 * NPIX];                // activated hidden
__device__ float g_boxes[NBOX * 4];
__device__ float g_conf[NBOX];
__device__ unsigned long long g_items[SORT_CAP]; // (~conf_bits<<32)|idx
__device__ int g_count;
__device__ unsigned long long g_mask[(size_t)NBOX * NWORDS];
__device__ unsigned char g_keep[NBOX];

// ---------------- repack w1 (o,c,t)->(t,c,o) via smem transpose, init folded ----------------
// grid 1280 (= 8 o-blocks x 160 c-blocks), 256 threads
__global__ void __launch_bounds__(256) k_pre(const float* __restrict__ w1) {
    __shared__ float s[9][8][33];
    const int bid = blockIdx.x;
    const int ob = bid & 7, cb = bid >> 3;
    const int tid = threadIdx.x;
    const int gi = bid * 256 + tid;
    if (gi < SORT_CAP) g_items[gi] = ~0ULL;
    if (gi < NBOX)     g_keep[gi] = 0;
    if (gi == 0)       g_count = 0;

    const int o = tid >> 3, c = tid & 7;
    const float* src = w1 + ((size_t)(ob * 32 + o) * 1280 + cb * 8 + c) * 9;
#pragma unroll
    for (int t = 0; t < 9; t++) s[t][c][o] = src[t];
    __syncthreads();
#pragma unroll
    for (int k = 0; k < 9; k++) {
        int widx = tid + k * 256;
        int t   = widx >> 8;
        int rem = widx & 255;
        int cc  = rem >> 5, oo = rem & 31;
        g_w1t[(size_t)t * (1280 * 256) + (cb * 8 + cc) * 256 + ob * 32 + oo] = s[t][cc][oo];
    }
}

// ---------------- conv1: per-tap 128oc x 128px GEMM tile, f32x2 (measured-best R4 version) ----------------
// grid (2, 8, 9), 256 threads, 8 oc x 8 px per thread, K-tile 16
__global__ void __launch_bounds__(256) k_conv1(const float* __restrict__ feat) {
    __shared__ float As[2][16][128];
    __shared__ float Bs[2][16][128];

    const int ocBase = blockIdx.x * 128;
    const int p0     = blockIdx.y * 128;
    const int tp     = blockIdx.z;
    const int dy = tp / 3 - 1, dx = tp % 3 - 1;
    const int sh = dy * 32 + dx;

    const int tid = threadIdx.x;
    const int arow = tid >> 5;
    const int acol = (tid & 31) * 4;
    const int bpx  = tid & 127;
    const int brow = tid >> 7;
    const int p    = p0 + bpx;
    const int yy   = (p >> 5) + dy;
    const int xx   = (p & 31) + dx;
    const bool bok = ((unsigned)yy < 32u) && ((unsigned)xx < 32u);
    const int bsrc = p + sh;

    const float* wp = g_w1t + (size_t)tp * (1280 * 256) + ocBase;

    const int ty = tid >> 4;
    const int tx = tid & 15;

    unsigned long long acc[8][4];
#pragma unroll
    for (int i = 0; i < 8; i++)
#pragma unroll
        for (int j = 0; j < 4; j++) acc[i][j] = 0ull;

    float4 a_reg0, a_reg1;
    float  b_reg[8];

    a_reg0 = *(const float4*)(wp + arow * 256 + acol);
    a_reg1 = *(const float4*)(wp + (arow + 8) * 256 + acol);
#pragma unroll
    for (int i = 0; i < 8; i++) {
        int c = brow + i * 2;
        b_reg[i] = bok ? feat[c * 1024 + bsrc] : 0.f;
    }

    int buf = 0;
    for (int c0 = 0; c0 < 1280; c0 += 16) {
        *(float4*)&As[buf][arow][acol]     = a_reg0;
        *(float4*)&As[buf][arow + 8][acol] = a_reg1;
#pragma unroll
        for (int i = 0; i < 8; i++) Bs[buf][brow + i * 2][bpx] = b_reg[i];
        __syncthreads();

        if (c0 + 16 < 1280) {
            const int cn = c0 + 16;
            a_reg0 = *(const float4*)(wp + (cn + arow) * 256 + acol);
            a_reg1 = *(const float4*)(wp + (cn + arow + 8) * 256 + acol);
#pragma unroll
            for (int i = 0; i < 8; i++) {
                int c = cn + brow + i * 2;
                b_reg[i] = bok ? feat[c * 1024 + bsrc] : 0.f;
            }
        }

#pragma unroll
        for (int kk = 0; kk < 16; ++kk) {
            float4 a0 = *(const float4*)&As[buf][kk][ty * 8];
            float4 a1 = *(const float4*)&As[buf][kk][ty * 8 + 4];
            ulonglong2 bq0 = *(const ulonglong2*)&Bs[buf][kk][tx * 8];
            ulonglong2 bq1 = *(const ulonglong2*)&Bs[buf][kk][tx * 8 + 4];
            unsigned long long d;
            d = dup2(a0.x); FMA2(acc[0][0], d, bq0.x); FMA2(acc[0][1], d, bq0.y); FMA2(acc[0][2], d, bq1.x); FMA2(acc[0][3], d, bq1.y);
            d = dup2(a0.y); FMA2(acc[1][0], d, bq0.x); FMA2(acc[1][1], d, bq0.y); FMA2(acc[1][2], d, bq1.x); FMA2(acc[1][3], d, bq1.y);
            d = dup2(a0.z); FMA2(acc[2][0], d, bq0.x); FMA2(acc[2][1], d, bq0.y); FMA2(acc[2][2], d, bq1.x); FMA2(acc[2][3], d, bq1.y);
            d = dup2(a0.w); FMA2(acc[3][0], d, bq0.x); FMA2(acc[3][1], d, bq0.y); FMA2(acc[3][2], d, bq1.x); FMA2(acc[3][3], d, bq1.y);
            d = dup2(a1.x); FMA2(acc[4][0], d, bq0.x); FMA2(acc[4][1], d, bq0.y); FMA2(acc[4][2], d, bq1.x); FMA2(acc[4][3], d, bq1.y);
            d = dup2(a1.y); FMA2(acc[5][0], d, bq0.x); FMA2(acc[5][1], d, bq0.y); FMA2(acc[5][2], d, bq1.x); FMA2(acc[5][3], d, bq1.y);
            d = dup2(a1.z); FMA2(acc[6][0], d, bq0.x); FMA2(acc[6][1], d, bq0.y); FMA2(acc[6][2], d, bq1.x); FMA2(acc[6][3], d, bq1.y);
            d = dup2(a1.w); FMA2(acc[7][0], d, bq0.x); FMA2(acc[7][1], d, bq0.y); FMA2(acc[7][2], d, bq1.x); FMA2(acc[7][3], d, bq1.y);
        }
        buf ^= 1;
    }

    const int oc = ocBase + ty * 8;
    const int px = p0 + tx * 8;
#pragma unroll
    for (int i = 0; i < 8; i++) {
        float* dst = g_hp[tp] + (size_t)(oc + i) * 1024 + px;
#pragma unroll
        for (int j = 0; j < 4; j++)
            *(unsigned long long*)(dst + 2 * j) = acc[i][j];
    }
}

// ---------------- combine 9 partials + bias + leaky relu ----------------
__global__ void __launch_bounds__(256) k_act(const float* __restrict__ b1) {
    int i = blockIdx.x * 256 + threadIdx.x;   // 262144 total
    float v = g_hp[0][i];
#pragma unroll
    for (int z = 1; z < 9; z++) v += g_hp[z][i];
    v += b1[i >> 10];
    v = (v > 0.f) ? v : 0.01f * v;
    g_h[i] = v;
}

// ---------------- conv2 (1x1) split-K + sigmoid + decode + compaction ----------------
// grid 144 (= 9 anchors x 16 px-chunks), block 256 = 64 px x 4 channel segments
__global__ void __launch_bounds__(256) k_conv2(const float* __restrict__ w2,
                                               const float* __restrict__ b2,
                                               const float* __restrict__ anch) {
    __shared__ float sw[5][256];
    __shared__ float part[4][5][64];
    const int a  = blockIdx.x >> 4;
    const int pc = blockIdx.x & 15;
    const int tid = threadIdx.x;
    const int px  = tid & 63;
    const int seg = tid >> 6;           // 0..3
    const int F[5] = {0, 2, 3, 4, 5};
#pragma unroll
    for (int f = 0; f < 5; ++f)
        sw[f][tid] = w2[(a * 6 + F[f]) * 256 + tid];
    __syncthreads();

    const int p = pc * 64 + px;
    float s0 = 0.f, s1 = 0.f, s2 = 0.f, s3 = 0.f, s4 = 0.f;
    const int cbase = seg * 64;
#pragma unroll 8
    for (int cc = 0; cc < 64; ++cc) {
        const int c = cbase + cc;
        float hv = g_h[c * 1024 + p];
        s0 = fmaf(sw[0][c], hv, s0);
        s1 = fmaf(sw[1][c], hv, s1);
        s2 = fmaf(sw[2][c], hv, s2);
        s3 = fmaf(sw[3][c], hv, s3);
        s4 = fmaf(sw[4][c], hv, s4);
    }
    part[seg][0][px] = s0;
    part[seg][1][px] = s1;
    part[seg][2][px] = s2;
    part[seg][3][px] = s3;
    part[seg][4][px] = s4;
    __syncthreads();

    if (seg == 0) {
        float v[5];
#pragma unroll
        for (int f = 0; f < 5; ++f)
            v[f] = ((part[0][f][px] + part[1][f][px]) + part[2][f][px]) + part[3][f][px];
        float logit = v[0] + b2[a * 6 + 0];
        float tx = v[1] + b2[a * 6 + 2];
        float ty = v[2] + b2[a * 6 + 3];
        float tw = v[3] + b2[a * 6 + 4];
        float th = v[4] + b2[a * 6 + 5];
        float aw = anch[a * 2 + 0], ah = anch[a * 2 + 1];
        float cx = (float)(p & 31) + 0.5f;
        float cy = (float)(p >> 5) + 0.5f;
        float pcx = cx + tx * aw;
        float pcy = cy + ty * ah;
        float pw = aw * expf(tw);
        float ph = ah * expf(th);
        float conf = 1.0f / (1.0f + expf(-logit));
        int r = p * 9 + a;
        g_boxes[r * 4 + 0] = pcx - pw * 0.5f;
        g_boxes[r * 4 + 1] = pcy - ph * 0.5f;
        g_boxes[r * 4 + 2] = pcx + pw * 0.5f;
        g_boxes[r * 4 + 3] = pcy + ph * 0.5f;
        g_conf[r] = conf;
        if (conf > 0.5f) {
            int j = atomicAdd(&g_count, 1);
            unsigned int sb = __float_as_uint(conf);
            g_items[j] = ((unsigned long long)(~sb) << 32) | (unsigned int)r;
        }
    }
}

// ---------------- bitonic sort (ascending), 4096-elem shared chunks ----------------
__global__ void __launch_bounds__(1024) k_sort_local4k() {
    if (blockIdx.x >= 2 && g_count <= 8192) return;   // pad region: all keys equal
    __shared__ unsigned long long s[4096];
    const int base = blockIdx.x * 4096;
    const int tid = threadIdx.x;
#pragma unroll
    for (int e = 0; e < 4; e++) s[tid + e * 1024] = g_items[base + tid + e * 1024];
    __syncthreads();
    for (int k = 2; k <= 4096; k <<= 1) {
        for (int j = k >> 1; j > 0; j >>= 1) {
#pragma unroll
            for (int e = 0; e < 2; e++) {
                int t = tid + e * 1024;
                int i = ((t & ~(j - 1)) << 1) | (t & (j - 1));
                int l = i + j;
                bool up = (((base + i) & k) == 0);
                unsigned long long x = s[i], y = s[l];
                if (up ? (x > y) : (x < y)) { s[i] = y; s[l] = x; }
            }
            __syncthreads();
        }
    }
#pragma unroll
    for (int e = 0; e < 4; e++) g_items[base + tid + e * 1024] = s[tid + e * 1024];
}

__global__ void __launch_bounds__(1024) k_sort_global(int k, int j, int minN) {
    if (g_count <= minN) return;
    if (blockIdx.x >= 4 && g_count <= 8192) return;   // pad-only pairs: keys equal, no swap
    int t = blockIdx.x * 1024 + threadIdx.x;
    int i = ((t & ~(j - 1)) << 1) | (t & (j - 1));
    int l = i + j;
    bool up = ((i & k) == 0);
    unsigned long long x = g_items[i], y = g_items[l];
    if (up ? (x > y) : (x < y)) { g_items[i] = y; g_items[l] = x; }
}

__global__ void __launch_bounds__(1024) k_sort_finish4k(int k, int minN) {
    if (g_count <= minN) return;
    if (blockIdx.x >= 2 && g_count <= 8192) return;   // pad region: all keys equal
    __shared__ unsigned long long s[4096];
    const int base = blockIdx.x * 4096;
    const int tid = threadIdx.x;
#pragma unroll
    for (int e = 0; e < 4; e++) s[tid + e * 1024] = g_items[base + tid + e * 1024];
    __syncthreads();
    for (int j = 2048; j > 0; j >>= 1) {
#pragma unroll
        for (int e = 0; e < 2; e++) {
            int t = tid + e * 1024;
            int i = ((t & ~(j - 1)) << 1) | (t & (j - 1));
            int l = i + j;
            bool up = (((base + i) & k) == 0);
            unsigned long long x = s[i], y = s[l];
            if (up ? (x > y) : (x < y)) { s[i] = y; s[l] = x; }
        }
        __syncthreads();
    }
#pragma unroll
    for (int e = 0; e < 4; e++) g_items[base + tid + e * 1024] = s[tid + e * 1024];
}

// ---------------- NMS bitmask build: warp ballot, column boxes in registers ----------------
// grid (144,144) upper-triangular, 64 threads = 2 warps x 32 rows
__global__ void __launch_bounds__(64) k_mask() {
    const int n = g_count;
    const int rb = blockIdx.y, cb = blockIdx.x;
    if (cb < rb) return;
    if (rb * 64 >= n) return;
    if (cb * 64 >= n) return;
    __shared__ float4 srow[64];
    __shared__ float  sarea[64];
    const int tid = threadIdx.x;
    const int row_g = rb * 64 + tid;
    if (row_g < n) {
        int r = (unsigned int)g_items[row_g];
        float4 b = *(const float4*)&g_boxes[r * 4];
        srow[tid]  = b;
        sarea[tid] = fmaxf(b.z - b.x, 0.f) * fmaxf(b.w - b.y, 0.f);
    } else {
        srow[tid]  = make_float4(0.f, 0.f, 0.f, 0.f);
        sarea[tid] = 0.f;
    }
    __syncthreads();

    const int wrp = tid >> 5, lane = tid & 31;
    const int colA = cb * 64 + lane;
    const int colB = colA + 32;
    float4 bA = make_float4(0.f, 0.f, 0.f, 0.f);
    float4 bB = make_float4(0.f, 0.f, 0.f, 0.f);
    if (colA < n) bA = *(const float4*)&g_boxes[((unsigned int)g_items[colA]) * 4];
    if (colB < n) bB = *(const float4*)&g_boxes[((unsigned int)g_items[colB]) * 4];
    const float areaA = fmaxf(bA.z - bA.x, 0.f) * fmaxf(bA.w - bA.y, 0.f);
    const float areaB = fmaxf(bB.z - bB.x, 0.f) * fmaxf(bB.w - bB.y, 0.f);
    const bool okA = colA < n, okB = colB < n;

    const int rend = min(32, n - rb * 64 - wrp * 32);   // rows this warp writes
    for (int r8 = 0; r8 < rend; ++r8) {
        const int rl = wrp * 32 + r8;
        const int row = rb * 64 + rl;
        const float4 bi = srow[rl];
        const float ai = sarea[rl];

        float iwA = fmaxf(fminf(bi.z, bA.z) - fmaxf(bi.x, bA.x), 0.f);
        float ihA = fmaxf(fminf(bi.w, bA.w) - fmaxf(bi.y, bA.y), 0.f);
        float interA = iwA * ihA;
        float iouA = interA / (ai + areaA - interA + 1e-8f);
        bool pA = (iouA > 0.7f) && (colA > row) && okA;
        unsigned int wA = __ballot_sync(0xffffffffu, pA);

        float iwB = fmaxf(fminf(bi.z, bB.z) - fmaxf(bi.x, bB.x), 0.f);
        float ihB = fmaxf(fminf(bi.w, bB.w) - fmaxf(bi.y, bB.y), 0.f);
        float interB = iwB * ihB;
        float iouB = interB / (ai + areaB - interB + 1e-8f);
        bool pB = (iouB > 0.7f) && (colB > row) && okB;
        unsigned int wB = __ballot_sync(0xffffffffu, pB);

        if (lane == 0)
            g_mask[(size_t)row * NWORDS + cb] =
                (unsigned long long)wA | ((unsigned long long)wB << 32);
    }
}

// ---------------- greedy NMS reduce (R3 measured-best variant) ----------------
__global__ void __launch_bounds__(256) k_reduce() {
    __shared__ unsigned long long s_remv[NWORDS];
    __shared__ unsigned long long s_diag[64];
    __shared__ unsigned long long s_keepw;
    const int n = g_count;
    const int nb = (n + 63) >> 6;
    const int tid = threadIdx.x;
    for (int i = tid; i < NWORDS; i += 256) s_remv[i] = 0;
    __syncthreads();
    const int q   = tid & 3;
    const int off = tid >> 2;
    for (int w = 0; w < nb; ++w) {
        if (tid < 64) {
            int row = w * 64 + tid;
            s_diag[tid] = (row < n) ? g_mask[(size_t)row * NWORDS + w] : 0ULL;
        }
        __syncthreads();
        if (tid == 0) {
            unsigned long long cur = s_remv[w];
            int rem = n - w * 64;
            if (rem < 64) cur |= (~0ULL) << rem;
            unsigned long long keepw = 0;
#pragma unroll
            for (int b = 0; b < 64; ++b) {
                if (!((cur >> b) & 1ULL)) {
                    keepw |= 1ULL << b;
                    cur |= s_diag[b];
                }
            }
            s_remv[w] = cur;
            s_keepw = keepw;
        }
        __syncthreads();
        const unsigned long long kw = s_keepw;
        for (int w2 = w + 1 + off; w2 < nb; w2 += 64) {
            unsigned long long accv = 0;
#pragma unroll
            for (int bb = 0; bb < 16; ++bb) {
                int b = q * 16 + bb;
                if ((kw >> b) & 1ULL)
                    accv |= g_mask[(size_t)(w * 64 + b) * NWORDS + w2];
            }
            if (accv) atomicOr(&s_remv[w2], accv);
        }
        __syncthreads();
        if (tid < 64) {
            if ((kw >> tid) & 1ULL) {
                int r = (unsigned int)g_items[w * 64 + tid];
                g_keep[r] = 1;
            }
        }
        __syncthreads();
    }
}

// ---------------- final output ----------------
__global__ void __launch_bounds__(256) k_output(float* __restrict__ out) {
    int i = blockIdx.x * 256 + threadIdx.x;
    if (i >= NBOX) return;
    float k = g_keep[i] ? 1.0f : 0.0f;
    float4 b = *(const float4*)&g_boxes[i * 4];
    out[i * 5 + 0] = b.x * k;
    out[i * 5 + 1] = b.y * k;
    out[i * 5 + 2] = b.z * k;
    out[i * 5 + 3] = b.w * k;
    out[i * 5 + 4] = g_conf[i] * k;
}

// ---------------- launch ----------------
extern "C" void kernel_launch(void* const* d_in, const int* in_sizes, int n_in,
                              void* d_out, int out_size) {
    const float *feat = nullptr, *anch = nullptr, *w1 = nullptr,
                *b1 = nullptr, *w2 = nullptr, *b2 = nullptr;
    for (int i = 0; i < n_in; ++i) {
        switch (in_sizes[i]) {
            case 1310720: feat = (const float*)d_in[i]; break;
            case 18:      anch = (const float*)d_in[i]; break;
            case 2949120: w1   = (const float*)d_in[i]; break;
            case 256:     b1   = (const float*)d_in[i]; break;
            case 13824:   w2   = (const float*)d_in[i]; break;
            case 54:      b2   = (const float*)d_in[i]; break;
            default: break;
        }
    }
    float* out = (float*)d_out;

    k_pre<<<1280, 256>>>(w1);                       // 0 (repack + init)
    k_conv1<<<dim3(2, 8, 9), 256>>>(feat);          // 1
    k_act<<<1024, 256>>>(b1);                       // 2
    k_conv2<<<144, 256>>>(w2, b2, anch);            // 3 <- ncu capture slot (verify fix)

    k_sort_local4k<<<4, 1024>>>();                  // 4
    k_sort_global<<<8, 1024>>>(8192, 4096, 4096);   // 5
    k_sort_finish4k<<<4, 1024>>>(8192, 4096);       // 6
    k_sort_global<<<8, 1024>>>(16384, 8192, 8192);  // 7
    k_sort_global<<<8, 1024>>>(16384, 4096, 8192);  // 8
    k_sort_finish4k<<<4, 1024>>>(16384, 8192);      // 9

    k_mask<<<dim3(144, 144), 64>>>();               // 10
    k_reduce<<<1, 256>>>();                         // 11
    k_output<<<36, 256>>>(out);                     // 12
}